// round 10
// baseline (speedup 1.0000x reference)
#include <cuda_runtime.h>
#include <cuda_fp16.h>
#include <cstdint>

// ---------------- problem constants ----------------
#define BQ 16
#define HQ 256
#define NLEAF 15625
#define NINT 3906
#define TMG 128
#define TNG 128
#define KC 64
#define NSTAGE 20
#define STAGE_BYTES 32768          // A 16K | B 16K
#define SMEM_BYTES (4096 + 3 * STAGE_BYTES)
#define NBLK 296

// ---------------- static device scratch ----------------
__device__ __half g_fA[(size_t)BQ * NLEAF * HQ];   // 128 MB
__device__ __half g_fB[BQ * 3125 * HQ];
__device__ __half g_WT[3 * HQ * 1280];             // [t][n][k] fp16
__device__ float g_part[266 * 16384];              // split-K partials (~17.4 MB)
__device__ int g_perm[65536];
__device__ int g_count[18];
__device__ int g_cursor[18];
__device__ int g_seg[24];
__device__ int g_barc;
__device__ volatile int g_bars;

__constant__ int c_n[6]     = {1, 5, 25, 125, 625, 3125};
__constant__ int c_off[6]   = {0, 1, 6, 31, 156, 781};
__constant__ int c_cumM[7]  = {0, 16, 96, 496, 2496, 12496, 62496};
__constant__ int c_pbase[6] = {0, 512, 1024, 2048, 4608, 15104};

// ---------------- helpers ----------------
__device__ __forceinline__ uint32_t smem_u32(const void* p) {
    uint32_t a;
    asm("{ .reg .u64 t; cvta.to.shared.u64 t, %1; cvt.u32.u64 %0, t; }" : "=r"(a) : "l"(p));
    return a;
}
#define SWZ(x) ((x) ^ (((x) >> 3) & 0x70))

#define CP16(d, s)  asm volatile("cp.async.cg.shared.global [%0], [%1], 16;" :: "r"(d), "l"(s) : "memory")
#define CP_COMMIT() asm volatile("cp.async.commit_group;" ::: "memory")
#define CP_WAIT2()  asm volatile("cp.async.wait_group 2;" ::: "memory")

__device__ __forceinline__ void ldm4(uint32_t addr, uint32_t* r) {
    asm volatile("ldmatrix.sync.aligned.m8n8.x4.shared.b16 {%0,%1,%2,%3}, [%4];"
                 : "=r"(r[0]), "=r"(r[1]), "=r"(r[2]), "=r"(r[3]) : "r"(addr));
}
__device__ __forceinline__ void mma16816(float* c, const uint32_t* a, const uint32_t* b) {
    asm volatile(
        "mma.sync.aligned.m16n8k16.row.col.f32.f16.f16.f32 "
        "{%0,%1,%2,%3}, {%4,%5,%6,%7}, {%8,%9}, {%0,%1,%2,%3};"
        : "+f"(c[0]), "+f"(c[1]), "+f"(c[2]), "+f"(c[3])
        : "r"(a[0]), "r"(a[1]), "r"(a[2]), "r"(a[3]), "r"(b[0]), "r"(b[1]));
}

// sense-monotonic global barrier over NBLK resident blocks
__device__ __forceinline__ void gbar(int& sense) {
    __syncthreads();
    if (threadIdx.x == 0) {
        int s = sense + 1;
        __threadfence();
        if (atomicAdd(&g_barc, 1) == NBLK - 1) {
            g_barc = 0;
            __threadfence();
            g_bars = s;
        } else {
            while (g_bars < s) { __nanosleep(32); }
            __threadfence();
        }
    }
    __syncthreads();
    sense += 1;
}

// ---------------- prep kernels ----------------
__global__ void k_reset() {
    int i = threadIdx.x;
    if (i < 18) { g_count[i] = 0; g_cursor[i] = 0; }
    if (i == 0) { g_barc = 0; g_bars = 0; }
}

__device__ __forceinline__ void decode_row(int r, int& l, int& pr, int& b, int& j) {
    l = 0;
    while (r >= c_cumM[l + 1]) l++;
    pr = r - c_cumM[l];
    int n = c_n[l];
    b = pr / n;
    j = pr - b * n;
}

__global__ void k_count(const int* __restrict__ nt) {
    __shared__ int sc[18];
    int tid = threadIdx.x;
    if (tid < 18) sc[tid] = 0;
    __syncthreads();
    int r = blockIdx.x * blockDim.x + tid;
    if (r < 62496) {
        int l, pr, b, j;
        decode_row(r, l, pr, b, j);
        int t = nt[b * NINT + c_off[l] + j];
        atomicAdd(&sc[l * 3 + t], 1);
    }
    __syncthreads();
    if (tid < 18 && sc[tid]) atomicAdd(&g_count[tid], sc[tid]);
}

__global__ void k_scan() {
    if (threadIdx.x == 0) {
        for (int l = 0; l < 6; l++) {
            int base = 0;
            for (int t = 0; t < 3; t++) {
                g_seg[l * 4 + t] = base;
                base += ((g_count[l * 3 + t] + TMG - 1) / TMG) * TMG;
            }
            g_seg[l * 4 + 3] = base;
        }
    }
}

__global__ void k_scatter(const int* __restrict__ nt) {
    __shared__ int sc[18], sbase[18];
    int tid = threadIdx.x;
    if (tid < 18) sc[tid] = 0;
    __syncthreads();
    int r = blockIdx.x * blockDim.x + tid;
    int lt = -1, lpos = 0, l = 0, pr = 0;
    if (r < 62496) {
        int b, j;
        decode_row(r, l, pr, b, j);
        int t = nt[b * NINT + c_off[l] + j];
        lt = l * 3 + t;
        lpos = atomicAdd(&sc[lt], 1);
    }
    __syncthreads();
    if (tid < 18 && sc[tid]) sbase[tid] = atomicAdd(&g_cursor[tid], sc[tid]);
    __syncthreads();
    if (lt >= 0) {
        int t = lt - l * 3;
        g_perm[c_pbase[l] + g_seg[l * 4 + t] + sbase[lt] + lpos] = pr;
    }
}

// W_node (3,1280,256) -> [t][n][k] fp16, coalesced 32x32 tile transpose
__global__ __launch_bounds__(256) void k_wt(const float* __restrict__ Wn) {
    __shared__ float tile[32][33];
    int bid = blockIdx.x;
    int nb = bid & 7;
    int kb = (bid >> 3) % 40;
    int t  = bid / 320;
    int tx = threadIdx.x & 31;
    int ty = threadIdx.x >> 5;
#pragma unroll
    for (int s = 0; s < 4; s++) {
        int kk = ty + s * 8;
        tile[kk][tx] = Wn[((size_t)t * 1280 + kb * 32 + kk) * HQ + nb * 32 + tx];
    }
    __syncthreads();
#pragma unroll
    for (int s = 0; s < 4; s++) {
        int rr = ty + s * 8;
        g_WT[((size_t)t * HQ + nb * 32 + rr) * 1280 + kb * 32 + tx] =
            __float2half(tile[tx][rr]);
    }
}

// ---------------- leaf encoder ----------------
__global__ __launch_bounds__(256) void k_leaf(
    const float* __restrict__ lbox, const float* __restrict__ lsem,
    const float* __restrict__ Wb, const float* __restrict__ bb,
    const float* __restrict__ Ws, const float* __restrict__ bs) {
    __shared__ float sbox[4][4];
    __shared__ float ssem[4][16];
    int tid = threadIdx.x;
    long row0 = (long)blockIdx.x * 4;
    if (tid < 16) sbox[tid >> 2][tid & 3] = lbox[row0 * 4 + tid];
    if (tid < 64) ssem[tid >> 4][tid & 15] = lsem[row0 * 16 + tid];
    __syncthreads();
    int r = tid >> 6;
    int c = (tid & 63) * 4;
    long row = row0 + r;
    float4 a = *(const float4*)(bb + c);
    float acc[4] = {a.x, a.y, a.z, a.w};
#pragma unroll
    for (int q = 0; q < 4; q++) {
        float4 w = *(const float4*)(Wb + q * HQ + c);
        float x = sbox[r][q];
        acc[0] = fmaf(x, w.x, acc[0]); acc[1] = fmaf(x, w.y, acc[1]);
        acc[2] = fmaf(x, w.z, acc[2]); acc[3] = fmaf(x, w.w, acc[3]);
    }
    float4 a2 = *(const float4*)(bs + c);
    float acs[4] = {a2.x, a2.y, a2.z, a2.w};
#pragma unroll
    for (int q = 0; q < 16; q++) {
        float4 w = *(const float4*)(Ws + q * HQ + c);
        float x = ssem[r][q];
        acs[0] = fmaf(x, w.x, acs[0]); acs[1] = fmaf(x, w.y, acs[1]);
        acs[2] = fmaf(x, w.z, acs[2]); acs[3] = fmaf(x, w.w, acs[3]);
    }
    uint32_t p[2];
#pragma unroll
    for (int i = 0; i < 4; i += 2) {
        float v0 = fmaxf(acc[i], 0.f) + fmaxf(acs[i], 0.f);
        float v1 = fmaxf(acc[i + 1], 0.f) + fmaxf(acs[i + 1], 0.f);
        __half2 h2 = __floats2half2_rn(v0, v1);
        p[i >> 1] = *(uint32_t*)&h2;
    }
    *(uint2*)(g_fA + row * HQ + c) = make_uint2(p[0], p[1]);
}

// ---------------- common GEMM pieces ----------------
__device__ __forceinline__ void load_stage(
    uint32_t base, int k0, int t, int n0, int tid,
    const __half* __restrict__ src, const int* __restrict__ s_ab) {
#pragma unroll
    for (int i = 0; i < 4; i++) {
        int it = tid + i * 256;
        int row = (it >> 3) & 127;
        int ch = it & 7;
        const __half* sp = src + (size_t)s_ab[row] + k0 + ch * 8;
        uint32_t off = (uint32_t)(row * 128 + ch * 16);
        CP16(base + SWZ(off), sp);
    }
    const __half* wh = g_WT + (size_t)t * HQ * 1280;
    uint32_t bbase = base + 16384;
#pragma unroll
    for (int i = 0; i < 4; i++) {
        int it = tid + i * 256;
        int row = (it >> 3) & 127;
        int ch = it & 7;
        const __half* sp = wh + (size_t)(n0 + row) * 1280 + k0 + ch * 8;
        uint32_t off = (uint32_t)(row * 128 + ch * 16);
        CP16(bbase + SWZ(off), sp);
    }
}

__device__ __forceinline__ void tile_setup(
    char* smem, int lvl, int t, int m0, int n0, int tid,
    const float* __restrict__ Wb, const float* __restrict__ bb,
    const float* __restrict__ bn) {
    int*   s_pr    = (int*)(smem);
    int*   s_ab    = (int*)(smem + 512);
    float* s_wbox  = (float*)(smem + 1024);
    float* s_bbox  = (float*)(smem + 3072);
    float* s_bnode = (float*)(smem + 3584);
    if (tid < TMG) {
        int idx = m0 + tid;
        int lim = g_seg[lvl * 4 + t] + g_count[lvl * 3 + t];
        int pr = (idx < lim) ? g_perm[c_pbase[lvl] + idx] : -1;
        s_pr[tid] = pr;
        s_ab[tid] = (pr < 0 ? 0 : pr) * 1280;
    }
    if (tid < 128) {
#pragma unroll
        for (int q = 0; q < 4; q++) s_wbox[q * 128 + tid] = Wb[q * HQ + n0 + tid];
        s_bbox[tid] = bb[n0 + tid];
        s_bnode[tid] = bn[t * HQ + n0 + tid];
    }
}

__device__ __forceinline__ void epilogue(
    char* smem, float (*acc)[4][4], int wm, int wn, int lid,
    int n, int off, int n0, const float* __restrict__ ibox, __half* __restrict__ dst) {
    int*   s_pr    = (int*)(smem);
    float* s_wbox  = (float*)(smem + 1024);
    float* s_bbox  = (float*)(smem + 3072);
    float* s_bnode = (float*)(smem + 3584);
    int lq = lid >> 2, lr = (lid & 3) * 2;
#pragma unroll
    for (int mt = 0; mt < 4; mt++) {
#pragma unroll
        for (int h2 = 0; h2 < 2; h2++) {
            int m = wm * 64 + mt * 16 + lq + h2 * 8;
            int pr = s_pr[m];
            if (pr < 0) continue;
            int b = pr / n, j = pr - b * n;
            float4 bx = *(const float4*)(ibox + ((size_t)b * NINT + off + j) * 4);
#pragma unroll
            for (int nt = 0; nt < 4; nt++) {
                int cl = wn * 32 + nt * 8 + lr;
                float o[2];
#pragma unroll
                for (int u = 0; u < 2; u++) {
                    float be = s_bbox[cl + u];
                    be = fmaf(bx.x, s_wbox[cl + u], be);
                    be = fmaf(bx.y, s_wbox[128 + cl + u], be);
                    be = fmaf(bx.z, s_wbox[256 + cl + u], be);
                    be = fmaf(bx.w, s_wbox[384 + cl + u], be);
                    float v = acc[mt][nt][h2 * 2 + u] + s_bnode[cl + u];
                    o[u] = fmaxf(v, 0.f) + fmaxf(be, 0.f);
                }
                __half2 hv = __floats2half2_rn(o[0], o[1]);
                *(uint32_t*)(dst + (size_t)pr * HQ + n0 + cl) = *(uint32_t*)&hv;
            }
        }
    }
}

__device__ __forceinline__ void gemm_main(
    uint32_t sb, char* smem, int kbase, int nst, int t, int n0, int tid,
    int wm, int wn, int lid, const __half* __restrict__ src,
    float (*acc)[4][4]) {
    int* s_ab = (int*)(smem + 512);
    load_stage(sb + 4096, kbase, t, n0, tid, src, s_ab);
    CP_COMMIT();
    load_stage(sb + 4096 + STAGE_BYTES, kbase + KC, t, n0, tid, src, s_ab);
    CP_COMMIT();

    int a_lrow = lid & 15;
    int a_lcol = (lid >> 4) & 1;
    int b_nrow = (lid & 7) | ((lid >> 1) & 8);
    int b_kcol = (lid >> 3) & 1;

    int stg = 0;
    for (int s = 0; s < nst; s++) {
        if (s + 2 < nst) {
            int ns = stg + 2; if (ns >= 3) ns -= 3;
            load_stage(sb + 4096 + ns * STAGE_BYTES, kbase + (s + 2) * KC, t, n0, tid, src, s_ab);
        }
        CP_COMMIT();
        CP_WAIT2();
        __syncthreads();

        uint32_t base = sb + 4096 + stg * STAGE_BYTES;
#pragma unroll
        for (int ks = 0; ks < 4; ks++) {
            uint32_t ah[4][4], bh[4][2];
#pragma unroll
            for (int mt = 0; mt < 4; mt++) {
                uint32_t offA = (uint32_t)((wm * 64 + mt * 16 + a_lrow) * 128 + ks * 32 + a_lcol * 16);
                ldm4(base + SWZ(offA), ah[mt]);
            }
#pragma unroll
            for (int np = 0; np < 2; np++) {
                uint32_t offB = (uint32_t)((wn * 32 + np * 16 + b_nrow) * 128 + ks * 32 + b_kcol * 16);
                uint32_t r[4];
                ldm4(base + 16384 + SWZ(offB), r);
                bh[2 * np][0] = r[0]; bh[2 * np][1] = r[1];
                bh[2 * np + 1][0] = r[2]; bh[2 * np + 1][1] = r[3];
            }
#pragma unroll
            for (int mt = 0; mt < 4; mt++)
#pragma unroll
                for (int nt = 0; nt < 4; nt++)
                    mma16816(acc[mt][nt], ah[mt], bh[nt]);
        }
        __syncthreads();
        stg++; if (stg >= 3) stg = 0;
    }
}

// ---------------- persistent mega kernel: levels 5..0 + head ----------------
__global__ __launch_bounds__(256, 2) void k_mega(
    const float* __restrict__ ibox, const float* __restrict__ bn,
    const float* __restrict__ Wb, const float* __restrict__ bb,
    const float* __restrict__ eps,
    const float* __restrict__ W1, const float* __restrict__ b1,
    const float* __restrict__ Wmu, const float* __restrict__ bmu,
    const float* __restrict__ Wvar, const float* __restrict__ bvar,
    float* __restrict__ out) {
    extern __shared__ __align__(128) char smem[];
    uint32_t sb = smem_u32(smem);
    int tid = threadIdx.x, wid = tid >> 5, lid = tid & 31;
    int wm = wid & 1, wn = wid >> 1;
    int bid = blockIdx.x;
    int sense = 0;

    const int L_srcA[6]  = {1, 0, 1, 0, 1, 0};
    const int L_tiles[6] = {788, 164, 38, 14, 8, 8};
    const int L_split[6] = {1, 1, 7, 10, 10, 10};

    for (int ph = 0; ph < 6; ph++) {
        int lvl = 5 - ph;
        int srcA = L_srcA[ph];
        int tiles = L_tiles[ph], split = L_split[ph];
        int q = NSTAGE / split, r = NSTAGE % split;
        const __half* src = srcA ? g_fA : g_fB;
        __half* dst = srcA ? g_fB : g_fA;
        int n = c_n[lvl], off = c_off[lvl];
        int total = g_seg[lvl * 4 + 3];

        for (int u = bid; u < tiles * split; u += NBLK) {
            int ti = u % tiles, z = u / tiles;
            int m0 = (ti >> 1) * TMG;
            if (m0 >= total) continue;
            int n0 = (ti & 1) * TNG;
            int t = (m0 >= g_seg[lvl * 4 + 2]) ? 2 : (m0 >= g_seg[lvl * 4 + 1]) ? 1 : 0;

            tile_setup(smem, lvl, t, m0, n0, tid, Wb, bb, bn);
            __syncthreads();

            float acc[4][4][4];
#pragma unroll
            for (int i = 0; i < 4; i++)
#pragma unroll
                for (int j = 0; j < 4; j++)
#pragma unroll
                    for (int p2 = 0; p2 < 4; p2++) acc[i][j][p2] = 0.f;

            int stg0 = z * q + (z < r ? z : r);
            int nst = q + (z < r ? 1 : 0);
            gemm_main(sb, smem, stg0 * KC, nst, t, n0, tid, wm, wn, lid, src, acc);

            if (split == 1) {
                epilogue(smem, acc, wm, wn, lid, n, off, n0, ibox, dst);
            } else {
                float* part = g_part + (size_t)(z * tiles + ti) * 16384;
                int lq = lid >> 2, lr = (lid & 3) * 2;
#pragma unroll
                for (int mt = 0; mt < 4; mt++)
#pragma unroll
                    for (int h2 = 0; h2 < 2; h2++) {
                        int m = wm * 64 + mt * 16 + lq + h2 * 8;
#pragma unroll
                        for (int nt = 0; nt < 4; nt++) {
                            int cl = wn * 32 + nt * 8 + lr;
                            *(float2*)(part + m * 128 + cl) =
                                make_float2(acc[mt][nt][h2 * 2], acc[mt][nt][h2 * 2 + 1]);
                        }
                    }
            }
            __syncthreads();
        }
        gbar(sense);

        if (split > 1) {
            for (int u = bid; u < tiles; u += NBLK) {
                int ti = u;
                int m0 = (ti >> 1) * TMG;
                if (m0 >= total) continue;
                int n0 = (ti & 1) * TNG;
                int t = (m0 >= g_seg[lvl * 4 + 2]) ? 2 : (m0 >= g_seg[lvl * 4 + 1]) ? 1 : 0;
                tile_setup(smem, lvl, t, m0, n0, tid, Wb, bb, bn);
                __syncthreads();

                int*   s_pr    = (int*)(smem);
                float* s_wbox  = (float*)(smem + 1024);
                float* s_bbox  = (float*)(smem + 3072);
                float* s_bnode = (float*)(smem + 3584);

                int row = tid >> 1;
                int c0 = (tid & 1) * 64;
                int pr = s_pr[row];
                if (pr >= 0) {
                    int b = pr / n, j = pr - b * n;
                    float4 bx = *(const float4*)(ibox + ((size_t)b * NINT + off + j) * 4);
                    const float* part = g_part + (size_t)ti * 16384 + row * 128;
                    size_t zstride = (size_t)tiles * 16384;
                    for (int c = 0; c < 64; c += 2) {
                        int cl = c0 + c;
                        float2 v = *(const float2*)(part + cl);
                        for (int zz = 1; zz < split; zz++) {
                            float2 w = *(const float2*)(part + zz * zstride + cl);
                            v.x += w.x; v.y += w.y;
                        }
                        float vv[2] = {v.x, v.y};
                        float o[2];
#pragma unroll
                        for (int uu = 0; uu < 2; uu++) {
                            float be = s_bbox[cl + uu];
                            be = fmaf(bx.x, s_wbox[cl + uu], be);
                            be = fmaf(bx.y, s_wbox[128 + cl + uu], be);
                            be = fmaf(bx.z, s_wbox[256 + cl + uu], be);
                            be = fmaf(bx.w, s_wbox[384 + cl + uu], be);
                            o[uu] = fmaxf(vv[uu] + s_bnode[cl + uu], 0.f) + fmaxf(be, 0.f);
                        }
                        __half2 hv = __floats2half2_rn(o[0], o[1]);
                        *(uint32_t*)(dst + (size_t)pr * HQ + n0 + cl) = *(uint32_t*)&hv;
                    }
                }
                __syncthreads();
            }
            gbar(sense);
        }
    }

    // ---- head phase (roots are in g_fA rows 0..BQ-1) ----
    if (bid < BQ) {
        float* sroot = (float*)(smem);
        float* senc  = (float*)(smem + 1024);
        int b = bid, h = tid;
        sroot[h] = __half2float(g_fA[b * HQ + h]);
        __syncthreads();
        float a = b1[h];
        for (int k = 0; k < HQ; k++) a = fmaf(sroot[k], W1[k * HQ + h], a);
        senc[h] = fmaxf(a, 0.f);
        __syncthreads();
        float mu = bmu[h], lv = bvar[h];
        for (int k = 0; k < HQ; k++) {
            float e = senc[k];
            mu = fmaf(e, Wmu[k * HQ + h], mu);
            lv = fmaf(e, Wvar[k * HQ + h], lv);
        }
        float stdv = expf(0.5f * lv);
        out[b * 2 * HQ + h] = eps[b * HQ + h] * stdv + mu;
        out[b * 2 * HQ + HQ + h] = 1.f + lv - mu * mu - expf(lv);
    }
}

// ---------------- launch ----------------
extern "C" void kernel_launch(void* const* d_in, const int* in_sizes, int n_in,
                              void* d_out, int out_size) {
    const float* leaf_box     = (const float*)d_in[0];
    const float* leaf_sem     = (const float*)d_in[1];
    const float* internal_box = (const float*)d_in[2];
    const int*   node_type    = (const int*)d_in[3];
    const float* eps          = (const float*)d_in[4];
    const float* W_box        = (const float*)d_in[5];
    const float* b_box        = (const float*)d_in[6];
    const float* W_sem        = (const float*)d_in[7];
    const float* b_sem        = (const float*)d_in[8];
    const float* W_node       = (const float*)d_in[9];
    const float* b_node       = (const float*)d_in[10];
    const float* W1           = (const float*)d_in[11];
    const float* b1           = (const float*)d_in[12];
    const float* Wmu          = (const float*)d_in[13];
    const float* bmu          = (const float*)d_in[14];
    const float* Wvar         = (const float*)d_in[15];
    const float* bvar         = (const float*)d_in[16];
    float* out = (float*)d_out;

    cudaFuncSetAttribute(k_mega, cudaFuncAttributeMaxDynamicSharedMemorySize, SMEM_BYTES);

    k_reset<<<1, 64>>>();
    k_count<<<(62496 + 255) / 256, 256>>>(node_type);
    k_scan<<<1, 32>>>();
    k_scatter<<<(62496 + 255) / 256, 256>>>(node_type);
    k_wt<<<960, 256>>>(W_node);
    k_leaf<<<(BQ * NLEAF + 3) / 4, 256>>>(leaf_box, leaf_sem, W_box, b_box, W_sem, b_sem);

    k_mega<<<NBLK, 256, SMEM_BYTES>>>(internal_box, b_node, W_box, b_box,
                                      eps, W1, b1, Wmu, bmu, Wvar, bvar, out);
}

// round 11
// speedup vs baseline: 1.7079x; 1.7079x over previous
#include <cuda_runtime.h>
#include <cuda_fp16.h>
#include <cstdint>

// ---------------- problem constants ----------------
#define BQ 16
#define HQ 256
#define NLEAF 15625
#define NINT 3906
#define NROWS (BQ * NLEAF)
#define TMG 128
#define TNG 128
#define KC 64
#define NSTAGE 20
#define STAGE_BYTES 32768          // A 16K | B 16K
#define SMEM_BYTES (4096 + 3 * STAGE_BYTES)

// ---------------- static device scratch ----------------
__device__ __half g_fA[(size_t)NROWS * HQ];        // 128 MB
__device__ __half g_fB[BQ * 3125 * HQ];
__device__ __half g_WT[3 * HQ * 1280];             // [t][n][k] fp16
__device__ int g_perm[65536];
__device__ int g_count[18];
__device__ int g_cursor[18];
__device__ int g_seg[24];

__constant__ int c_n[6]     = {1, 5, 25, 125, 625, 3125};
__constant__ int c_off[6]   = {0, 1, 6, 31, 156, 781};
__constant__ int c_cumM[7]  = {0, 16, 96, 496, 2496, 12496, 62496};
__constant__ int c_pbase[6] = {0, 512, 1024, 2048, 4608, 15104};

// ---------------- helpers ----------------
__device__ __forceinline__ uint32_t smem_u32(const void* p) {
    uint32_t a;
    asm("{ .reg .u64 t; cvta.to.shared.u64 t, %1; cvt.u32.u64 %0, t; }" : "=r"(a) : "l"(p));
    return a;
}
#define SWZ(x) ((x) ^ (((x) >> 3) & 0x70))

#define CP16(d, s)  asm volatile("cp.async.cg.shared.global [%0], [%1], 16;" :: "r"(d), "l"(s) : "memory")
#define CP_COMMIT() asm volatile("cp.async.commit_group;" ::: "memory")
#define CP_WAIT2()  asm volatile("cp.async.wait_group 2;" ::: "memory")

__device__ __forceinline__ void ldm4(uint32_t addr, uint32_t* r) {
    asm volatile("ldmatrix.sync.aligned.m8n8.x4.shared.b16 {%0,%1,%2,%3}, [%4];"
                 : "=r"(r[0]), "=r"(r[1]), "=r"(r[2]), "=r"(r[3]) : "r"(addr));
}
__device__ __forceinline__ void mma16816(float* c, const uint32_t* a, const uint32_t* b) {
    asm volatile(
        "mma.sync.aligned.m16n8k16.row.col.f32.f16.f16.f32 "
        "{%0,%1,%2,%3}, {%4,%5,%6,%7}, {%8,%9}, {%0,%1,%2,%3};"
        : "+f"(c[0]), "+f"(c[1]), "+f"(c[2]), "+f"(c[3])
        : "r"(a[0]), "r"(a[1]), "r"(a[2]), "r"(a[3]), "r"(b[0]), "r"(b[1]));
}

// ---------------- prep kernels ----------------
__global__ void k_reset() {
    int i = threadIdx.x;
    if (i < 18) { g_count[i] = 0; g_cursor[i] = 0; }
}

__device__ __forceinline__ void decode_row(int r, int& l, int& pr, int& b, int& j) {
    l = 0;
    while (r >= c_cumM[l + 1]) l++;
    pr = r - c_cumM[l];
    int n = c_n[l];
    b = pr / n;
    j = pr - b * n;
}

__global__ void k_count(const int* __restrict__ nt) {
    __shared__ int sc[18];
    int tid = threadIdx.x;
    if (tid < 18) sc[tid] = 0;
    __syncthreads();
    int r = blockIdx.x * blockDim.x + tid;
    if (r < 62496) {
        int l, pr, b, j;
        decode_row(r, l, pr, b, j);
        int t = nt[b * NINT + c_off[l] + j];
        atomicAdd(&sc[l * 3 + t], 1);
    }
    __syncthreads();
    if (tid < 18 && sc[tid]) atomicAdd(&g_count[tid], sc[tid]);
}

__global__ void k_scan() {
    if (threadIdx.x == 0) {
        for (int l = 0; l < 6; l++) {
            int base = 0;
            for (int t = 0; t < 3; t++) {
                g_seg[l * 4 + t] = base;
                base += ((g_count[l * 3 + t] + TMG - 1) / TMG) * TMG;
            }
            g_seg[l * 4 + 3] = base;
        }
    }
}

__global__ void k_scatter(const int* __restrict__ nt) {
    __shared__ int sc[18], sbase[18];
    int tid = threadIdx.x;
    if (tid < 18) sc[tid] = 0;
    __syncthreads();
    int r = blockIdx.x * blockDim.x + tid;
    int lt = -1, lpos = 0, l = 0, pr = 0;
    if (r < 62496) {
        int b, j;
        decode_row(r, l, pr, b, j);
        int t = nt[b * NINT + c_off[l] + j];
        lt = l * 3 + t;
        lpos = atomicAdd(&sc[lt], 1);
    }
    __syncthreads();
    if (tid < 18 && sc[tid]) sbase[tid] = atomicAdd(&g_cursor[tid], sc[tid]);
    __syncthreads();
    if (lt >= 0) {
        int t = lt - l * 3;
        g_perm[c_pbase[l] + g_seg[l * 4 + t] + sbase[lt] + lpos] = pr;
    }
}

// W_node (3,1280,256) -> [t][n][k] fp16, coalesced 32x32 tile transpose
__global__ __launch_bounds__(256) void k_wt(const float* __restrict__ Wn) {
    __shared__ float tile[32][33];
    int bid = blockIdx.x;
    int nb = bid & 7;
    int kb = (bid >> 3) % 40;
    int t  = bid / 320;
    int tx = threadIdx.x & 31;
    int ty = threadIdx.x >> 5;
#pragma unroll
    for (int s = 0; s < 4; s++) {
        int kk = ty + s * 8;
        tile[kk][tx] = Wn[((size_t)t * 1280 + kb * 32 + kk) * HQ + nb * 32 + tx];
    }
    __syncthreads();
#pragma unroll
    for (int s = 0; s < 4; s++) {
        int rr = ty + s * 8;
        g_WT[((size_t)t * HQ + nb * 32 + rr) * 1280 + kb * 32 + tx] =
            __float2half(tile[tx][rr]);
    }
}

// ---------------- leaf encoder: register-cached weights, 64 rows/block ----------------
__global__ __launch_bounds__(256) void k_leaf(
    const float* __restrict__ lbox, const float* __restrict__ lsem,
    const float* __restrict__ Wb, const float* __restrict__ bb,
    const float* __restrict__ Ws, const float* __restrict__ bs) {
    __shared__ float sbox[64][4];
    __shared__ float ssem[64][16];
    int tid = threadIdx.x;
    long row0 = (long)blockIdx.x * 64;

    // cooperative input load (64 rows)
    {
        long lim = (long)NROWS * 4;
        if (tid < 256) {
            long gi = row0 * 4 + tid;
            sbox[tid >> 2][tid & 3] = (gi < lim) ? lbox[gi] : 0.f;
        }
        long lim2 = (long)NROWS * 16;
#pragma unroll
        for (int i = tid; i < 1024; i += 256) {
            long gi = row0 * 16 + i;
            ssem[i >> 4][i & 15] = (gi < lim2) ? lsem[gi] : 0.f;
        }
    }
    __syncthreads();

    int colgrp = tid & 63;     // 64 column groups of 4
    int rowgrp = tid >> 6;     // 4 row groups of 16
    int c = colgrp * 4;

    // cache weights in registers
    float4 wb[4], ws[16];
#pragma unroll
    for (int q = 0; q < 4; q++)  wb[q] = *(const float4*)(Wb + q * HQ + c);
#pragma unroll
    for (int q = 0; q < 16; q++) ws[q] = *(const float4*)(Ws + q * HQ + c);
    float4 bbv = *(const float4*)(bb + c);
    float4 bsv = *(const float4*)(bs + c);

#pragma unroll 4
    for (int rr = 0; rr < 16; rr++) {
        int rl = rowgrp * 16 + rr;
        long row = row0 + rl;
        if (row >= NROWS) break;
        float acc[4] = {bbv.x, bbv.y, bbv.z, bbv.w};
#pragma unroll
        for (int q = 0; q < 4; q++) {
            float x = sbox[rl][q];
            acc[0] = fmaf(x, wb[q].x, acc[0]); acc[1] = fmaf(x, wb[q].y, acc[1]);
            acc[2] = fmaf(x, wb[q].z, acc[2]); acc[3] = fmaf(x, wb[q].w, acc[3]);
        }
        float acs[4] = {bsv.x, bsv.y, bsv.z, bsv.w};
#pragma unroll
        for (int q = 0; q < 16; q++) {
            float x = ssem[rl][q];
            acs[0] = fmaf(x, ws[q].x, acs[0]); acs[1] = fmaf(x, ws[q].y, acs[1]);
            acs[2] = fmaf(x, ws[q].z, acs[2]); acs[3] = fmaf(x, ws[q].w, acs[3]);
        }
        float v0 = fmaxf(acc[0], 0.f) + fmaxf(acs[0], 0.f);
        float v1 = fmaxf(acc[1], 0.f) + fmaxf(acs[1], 0.f);
        float v2 = fmaxf(acc[2], 0.f) + fmaxf(acs[2], 0.f);
        float v3 = fmaxf(acc[3], 0.f) + fmaxf(acs[3], 0.f);
        __half2 h0 = __floats2half2_rn(v0, v1);
        __half2 h1 = __floats2half2_rn(v2, v3);
        *(uint2*)(g_fA + row * HQ + c) =
            make_uint2(*(uint32_t*)&h0, *(uint32_t*)&h1);
    }
}

// ---------------- common GEMM pieces (R9, unchanged) ----------------
__device__ __forceinline__ void load_stage(
    uint32_t base, int k0, int t, int n0, int tid,
    const __half* __restrict__ src, const int* __restrict__ s_ab) {
#pragma unroll
    for (int i = 0; i < 4; i++) {
        int it = tid + i * 256;
        int row = (it >> 3) & 127;
        int ch = it & 7;
        const __half* sp = src + (size_t)s_ab[row] + k0 + ch * 8;
        uint32_t off = (uint32_t)(row * 128 + ch * 16);
        CP16(base + SWZ(off), sp);
    }
    const __half* wh = g_WT + (size_t)t * HQ * 1280;
    uint32_t bbase = base + 16384;
#pragma unroll
    for (int i = 0; i < 4; i++) {
        int it = tid + i * 256;
        int row = (it >> 3) & 127;
        int ch = it & 7;
        const __half* sp = wh + (size_t)(n0 + row) * 1280 + k0 + ch * 8;
        uint32_t off = (uint32_t)(row * 128 + ch * 16);
        CP16(bbase + SWZ(off), sp);
    }
}

__device__ __forceinline__ void tile_setup(
    char* smem, int lvl, int t, int m0, int n0, int tid,
    const float* __restrict__ Wb, const float* __restrict__ bb,
    const float* __restrict__ bn) {
    int*   s_pr    = (int*)(smem);
    int*   s_ab    = (int*)(smem + 512);
    float* s_wbox  = (float*)(smem + 1024);
    float* s_bbox  = (float*)(smem + 3072);
    float* s_bnode = (float*)(smem + 3584);
    if (tid < TMG) {
        int idx = m0 + tid;
        int lim = g_seg[lvl * 4 + t] + g_count[lvl * 3 + t];
        int pr = (idx < lim) ? g_perm[c_pbase[lvl] + idx] : -1;
        s_pr[tid] = pr;
        s_ab[tid] = (pr < 0 ? 0 : pr) * 1280;
    }
    if (tid < 128) {
#pragma unroll
        for (int q = 0; q < 4; q++) s_wbox[q * 128 + tid] = Wb[q * HQ + n0 + tid];
        s_bbox[tid] = bb[n0 + tid];
        s_bnode[tid] = bn[t * HQ + n0 + tid];
    }
}

__device__ __forceinline__ void epilogue(
    char* smem, float (*acc)[4][4], int wm, int wn, int lid,
    int n, int off, int n0, const float* __restrict__ ibox, __half* __restrict__ dst) {
    int*   s_pr    = (int*)(smem);
    float* s_wbox  = (float*)(smem + 1024);
    float* s_bbox  = (float*)(smem + 3072);
    float* s_bnode = (float*)(smem + 3584);
    int lq = lid >> 2, lr = (lid & 3) * 2;
#pragma unroll
    for (int mt = 0; mt < 4; mt++) {
#pragma unroll
        for (int h2 = 0; h2 < 2; h2++) {
            int m = wm * 64 + mt * 16 + lq + h2 * 8;
            int pr = s_pr[m];
            if (pr < 0) continue;
            int b = pr / n, j = pr - b * n;
            float4 bx = *(const float4*)(ibox + ((size_t)b * NINT + off + j) * 4);
#pragma unroll
            for (int nt = 0; nt < 4; nt++) {
                int cl = wn * 32 + nt * 8 + lr;
                float o[2];
#pragma unroll
                for (int u = 0; u < 2; u++) {
                    float be = s_bbox[cl + u];
                    be = fmaf(bx.x, s_wbox[cl + u], be);
                    be = fmaf(bx.y, s_wbox[128 + cl + u], be);
                    be = fmaf(bx.z, s_wbox[256 + cl + u], be);
                    be = fmaf(bx.w, s_wbox[384 + cl + u], be);
                    float v = acc[mt][nt][h2 * 2 + u] + s_bnode[cl + u];
                    o[u] = fmaxf(v, 0.f) + fmaxf(be, 0.f);
                }
                __half2 hv = __floats2half2_rn(o[0], o[1]);
                *(uint32_t*)(dst + (size_t)pr * HQ + n0 + cl) = *(uint32_t*)&hv;
            }
        }
    }
}

// ---------------- fixed-grid grouped GEMM (all levels; R9-proven) ----------------
__global__ __launch_bounds__(256, 2) void k_tc(
    int srcA, int lvl, int n, int off,
    const float* __restrict__ ibox, const float* __restrict__ bn,
    const float* __restrict__ Wb, const float* __restrict__ bb) {
    extern __shared__ __align__(128) char smem[];
    uint32_t sb = smem_u32(smem);
    int tid = threadIdx.x, wid = tid >> 5, lid = tid & 31;
    int wm = wid & 1, wn = wid >> 1;

    int m0 = blockIdx.y * TMG;
    int total = g_seg[lvl * 4 + 3];
    if (m0 >= total) return;
    int t = (m0 >= g_seg[lvl * 4 + 2]) ? 2 : (m0 >= g_seg[lvl * 4 + 1]) ? 1 : 0;
    int n0 = blockIdx.x * TNG;

    const __half* src = srcA ? g_fA : g_fB;
    __half* dst = srcA ? g_fB : g_fA;

    tile_setup(smem, lvl, t, m0, n0, tid, Wb, bb, bn);
    __syncthreads();

    int* s_ab = (int*)(smem + 512);
    load_stage(sb + 4096, 0, t, n0, tid, src, s_ab);
    CP_COMMIT();
    load_stage(sb + 4096 + STAGE_BYTES, KC, t, n0, tid, src, s_ab);
    CP_COMMIT();

    float acc[4][4][4];
#pragma unroll
    for (int i = 0; i < 4; i++)
#pragma unroll
        for (int j = 0; j < 4; j++)
#pragma unroll
            for (int q = 0; q < 4; q++) acc[i][j][q] = 0.f;

    int a_lrow = lid & 15;
    int a_lcol = (lid >> 4) & 1;
    int b_nrow = (lid & 7) | ((lid >> 1) & 8);
    int b_kcol = (lid >> 3) & 1;

    int stg = 0;
    for (int s = 0; s < NSTAGE; s++) {
        if (s + 2 < NSTAGE) {
            int ns = stg + 2; if (ns >= 3) ns -= 3;
            load_stage(sb + 4096 + ns * STAGE_BYTES, (s + 2) * KC, t, n0, tid, src, s_ab);
        }
        CP_COMMIT();
        CP_WAIT2();
        __syncthreads();

        uint32_t base = sb + 4096 + stg * STAGE_BYTES;
#pragma unroll
        for (int ks = 0; ks < 4; ks++) {
            uint32_t ah[4][4], bh[4][2];
#pragma unroll
            for (int mt = 0; mt < 4; mt++) {
                uint32_t offA = (uint32_t)((wm * 64 + mt * 16 + a_lrow) * 128 + ks * 32 + a_lcol * 16);
                ldm4(base + SWZ(offA), ah[mt]);
            }
#pragma unroll
            for (int np = 0; np < 2; np++) {
                uint32_t offB = (uint32_t)((wn * 32 + np * 16 + b_nrow) * 128 + ks * 32 + b_kcol * 16);
                uint32_t r[4];
                ldm4(base + 16384 + SWZ(offB), r);
                bh[2 * np][0] = r[0]; bh[2 * np][1] = r[1];
                bh[2 * np + 1][0] = r[2]; bh[2 * np + 1][1] = r[3];
            }
#pragma unroll
            for (int mt = 0; mt < 4; mt++)
#pragma unroll
                for (int nt = 0; nt < 4; nt++)
                    mma16816(acc[mt][nt], ah[mt], bh[nt]);
        }
        __syncthreads();
        stg++; if (stg >= 3) stg = 0;
    }

    epilogue(smem, acc, wm, wn, lid, n, off, n0, ibox, dst);
}

// ---------------- VAE head ----------------
__global__ void k_head(const float* __restrict__ eps,
                       const float* __restrict__ W1, const float* __restrict__ b1,
                       const float* __restrict__ Wmu, const float* __restrict__ bmu,
                       const float* __restrict__ Wvar, const float* __restrict__ bvar,
                       float* __restrict__ out) {
    int b = blockIdx.x;
    int h = threadIdx.x;
    __shared__ float sroot[HQ];
    __shared__ float senc[HQ];
    sroot[h] = __half2float(g_fA[b * HQ + h]);
    __syncthreads();
    float a = b1[h];
    for (int k = 0; k < HQ; k++) a = fmaf(sroot[k], W1[k * HQ + h], a);
    senc[h] = fmaxf(a, 0.f);
    __syncthreads();
    float mu = bmu[h], lv = bvar[h];
    for (int k = 0; k < HQ; k++) {
        float e = senc[k];
        mu = fmaf(e, Wmu[k * HQ + h], mu);
        lv = fmaf(e, Wvar[k * HQ + h], lv);
    }
    float stdv = expf(0.5f * lv);
    out[b * 2 * HQ + h] = eps[b * HQ + h] * stdv + mu;
    out[b * 2 * HQ + HQ + h] = 1.f + lv - mu * mu - expf(lv);
}

// ---------------- launch ----------------
extern "C" void kernel_launch(void* const* d_in, const int* in_sizes, int n_in,
                              void* d_out, int out_size) {
    const float* leaf_box     = (const float*)d_in[0];
    const float* leaf_sem     = (const float*)d_in[1];
    const float* internal_box = (const float*)d_in[2];
    const int*   node_type    = (const int*)d_in[3];
    const float* eps          = (const float*)d_in[4];
    const float* W_box        = (const float*)d_in[5];
    const float* b_box        = (const float*)d_in[6];
    const float* W_sem        = (const float*)d_in[7];
    const float* b_sem        = (const float*)d_in[8];
    const float* W_node       = (const float*)d_in[9];
    const float* b_node       = (const float*)d_in[10];
    const float* W1           = (const float*)d_in[11];
    const float* b1           = (const float*)d_in[12];
    const float* Wmu          = (const float*)d_in[13];
    const float* bmu          = (const float*)d_in[14];
    const float* Wvar         = (const float*)d_in[15];
    const float* bvar         = (const float*)d_in[16];
    float* out = (float*)d_out;

    cudaFuncSetAttribute(k_tc, cudaFuncAttributeMaxDynamicSharedMemorySize, SMEM_BYTES);

    k_reset<<<1, 64>>>();
    k_count<<<(62496 + 255) / 256, 256>>>(node_type);
    k_scan<<<1, 32>>>();
    k_scatter<<<(62496 + 255) / 256, 256>>>(node_type);
    k_wt<<<960, 256>>>(W_node);
    k_leaf<<<(NROWS + 63) / 64, 256>>>(leaf_box, leaf_sem, W_box, b_box, W_sem, b_sem);

    struct Lv { int srcA, lvl, n, off, gy; };
    const Lv lv[6] = {
        {1, 5, 3125, 781, 394},
        {0, 4,  625, 156,  82},
        {1, 3,  125,  31,  19},
        {0, 2,   25,   6,   7},
        {1, 1,    5,   1,   4},
        {0, 0,    1,   0,   4},
    };
    for (int i = 0; i < 6; i++) {
        dim3 grid(2, lv[i].gy);
        k_tc<<<grid, 256, SMEM_BYTES>>>(lv[i].srcA, lv[i].lvl, lv[i].n, lv[i].off,
                                        internal_box, b_node, W_box, b_box);
    }

    k_head<<<BQ, HQ>>>(eps, W1, b1, Wmu, bmu, Wvar, bvar, out);
}

// round 12
// speedup vs baseline: 1.9295x; 1.1298x over previous
#include <cuda_runtime.h>
#include <cuda_fp16.h>
#include <cstdint>

// ---------------- problem constants ----------------
#define BQ 16
#define HQ 256
#define NLEAF 15625
#define NINT 3906
#define NROWS (BQ * NLEAF)
#define TMG 128
#define TNG 128
#define KC 64
#define NSTAGE 20
#define STAGE_BYTES 32768          // A 16K | B 16K
#define SMEM_BYTES (4096 + 3 * STAGE_BYTES)
#define STAGE32 20480              // A 4K | B 16K
#define SMEM32 (4096 + 3 * STAGE32)

// ---------------- static device scratch ----------------
__device__ __half g_fA[(size_t)NROWS * HQ];        // 128 MB
__device__ __half g_fB[BQ * 3125 * HQ];
__device__ __half g_WT[3 * HQ * 1280];             // [t][n][k] fp16
__device__ int g_perm[65536];
__device__ int g_count[18];
__device__ int g_cursor[18];
__device__ int g_seg[24];

__constant__ int c_n[6]     = {1, 5, 25, 125, 625, 3125};
__constant__ int c_off[6]   = {0, 1, 6, 31, 156, 781};
__constant__ int c_cumM[7]  = {0, 16, 96, 496, 2496, 12496, 62496};
__constant__ int c_pbase[6] = {0, 512, 1024, 2048, 4608, 15104};

// ---------------- helpers ----------------
__device__ __forceinline__ uint32_t smem_u32(const void* p) {
    uint32_t a;
    asm("{ .reg .u64 t; cvta.to.shared.u64 t, %1; cvt.u32.u64 %0, t; }" : "=r"(a) : "l"(p));
    return a;
}
#define SWZ(x) ((x) ^ (((x) >> 3) & 0x70))

#define CP16(d, s)  asm volatile("cp.async.cg.shared.global [%0], [%1], 16;" :: "r"(d), "l"(s) : "memory")
#define CP_COMMIT() asm volatile("cp.async.commit_group;" ::: "memory")
#define CP_WAIT2()  asm volatile("cp.async.wait_group 2;" ::: "memory")

__device__ __forceinline__ void ldm4(uint32_t addr, uint32_t* r) {
    asm volatile("ldmatrix.sync.aligned.m8n8.x4.shared.b16 {%0,%1,%2,%3}, [%4];"
                 : "=r"(r[0]), "=r"(r[1]), "=r"(r[2]), "=r"(r[3]) : "r"(addr));
}
__device__ __forceinline__ void mma16816(float* c, const uint32_t* a, const uint32_t* b) {
    asm volatile(
        "mma.sync.aligned.m16n8k16.row.col.f32.f16.f16.f32 "
        "{%0,%1,%2,%3}, {%4,%5,%6,%7}, {%8,%9}, {%0,%1,%2,%3};"
        : "+f"(c[0]), "+f"(c[1]), "+f"(c[2]), "+f"(c[3])
        : "r"(a[0]), "r"(a[1]), "r"(a[2]), "r"(a[3]), "r"(b[0]), "r"(b[1]));
}

// ---------------- prep kernels ----------------
__global__ void k_reset() {
    int i = threadIdx.x;
    if (i < 18) { g_count[i] = 0; g_cursor[i] = 0; }
}

__device__ __forceinline__ void decode_row(int r, int& l, int& pr, int& b, int& j) {
    l = 0;
    while (r >= c_cumM[l + 1]) l++;
    pr = r - c_cumM[l];
    int n = c_n[l];
    b = pr / n;
    j = pr - b * n;
}

__global__ void k_count(const int* __restrict__ nt) {
    __shared__ int sc[18];
    int tid = threadIdx.x;
    if (tid < 18) sc[tid] = 0;
    __syncthreads();
    int r = blockIdx.x * blockDim.x + tid;
    if (r < 62496) {
        int l, pr, b, j;
        decode_row(r, l, pr, b, j);
        int t = nt[b * NINT + c_off[l] + j];
        atomicAdd(&sc[l * 3 + t], 1);
    }
    __syncthreads();
    if (tid < 18 && sc[tid]) atomicAdd(&g_count[tid], sc[tid]);
}

__global__ void k_scan() {
    if (threadIdx.x == 0) {
        for (int l = 0; l < 6; l++) {
            int base = 0;
            for (int t = 0; t < 3; t++) {
                g_seg[l * 4 + t] = base;
                base += ((g_count[l * 3 + t] + TMG - 1) / TMG) * TMG;
            }
            g_seg[l * 4 + 3] = base;
        }
    }
}

__global__ void k_scatter(const int* __restrict__ nt) {
    __shared__ int sc[18], sbase[18];
    int tid = threadIdx.x;
    if (tid < 18) sc[tid] = 0;
    __syncthreads();
    int r = blockIdx.x * blockDim.x + tid;
    int lt = -1, lpos = 0, l = 0, pr = 0;
    if (r < 62496) {
        int b, j;
        decode_row(r, l, pr, b, j);
        int t = nt[b * NINT + c_off[l] + j];
        lt = l * 3 + t;
        lpos = atomicAdd(&sc[lt], 1);
    }
    __syncthreads();
    if (tid < 18 && sc[tid]) sbase[tid] = atomicAdd(&g_cursor[tid], sc[tid]);
    __syncthreads();
    if (lt >= 0) {
        int t = lt - l * 3;
        g_perm[c_pbase[l] + g_seg[l * 4 + t] + sbase[lt] + lpos] = pr;
    }
}

// W_node (3,1280,256) -> [t][n][k] fp16, coalesced 32x32 tile transpose
__global__ __launch_bounds__(256) void k_wt(const float* __restrict__ Wn) {
    __shared__ float tile[32][33];
    int bid = blockIdx.x;
    int nb = bid & 7;
    int kb = (bid >> 3) % 40;
    int t  = bid / 320;
    int tx = threadIdx.x & 31;
    int ty = threadIdx.x >> 5;
#pragma unroll
    for (int s = 0; s < 4; s++) {
        int kk = ty + s * 8;
        tile[kk][tx] = Wn[((size_t)t * 1280 + kb * 32 + kk) * HQ + nb * 32 + tx];
    }
    __syncthreads();
#pragma unroll
    for (int s = 0; s < 4; s++) {
        int rr = ty + s * 8;
        g_WT[((size_t)t * HQ + nb * 32 + rr) * 1280 + kb * 32 + tx] =
            __float2half(tile[tx][rr]);
    }
}

// ---------------- leaf encoder: register-cached weights (R11-proven) ----------------
__global__ __launch_bounds__(256) void k_leaf(
    const float* __restrict__ lbox, const float* __restrict__ lsem,
    const float* __restrict__ Wb, const float* __restrict__ bb,
    const float* __restrict__ Ws, const float* __restrict__ bs) {
    __shared__ float sbox[64][4];
    __shared__ float ssem[64][16];
    int tid = threadIdx.x;
    long row0 = (long)blockIdx.x * 64;

    {
        long lim = (long)NROWS * 4;
        if (tid < 256) {
            long gi = row0 * 4 + tid;
            sbox[tid >> 2][tid & 3] = (gi < lim) ? lbox[gi] : 0.f;
        }
        long lim2 = (long)NROWS * 16;
#pragma unroll
        for (int i = tid; i < 1024; i += 256) {
            long gi = row0 * 16 + i;
            ssem[i >> 4][i & 15] = (gi < lim2) ? lsem[gi] : 0.f;
        }
    }
    __syncthreads();

    int colgrp = tid & 63;
    int rowgrp = tid >> 6;
    int c = colgrp * 4;

    float4 wb[4], ws[16];
#pragma unroll
    for (int q = 0; q < 4; q++)  wb[q] = *(const float4*)(Wb + q * HQ + c);
#pragma unroll
    for (int q = 0; q < 16; q++) ws[q] = *(const float4*)(Ws + q * HQ + c);
    float4 bbv = *(const float4*)(bb + c);
    float4 bsv = *(const float4*)(bs + c);

#pragma unroll 4
    for (int rr = 0; rr < 16; rr++) {
        int rl = rowgrp * 16 + rr;
        long row = row0 + rl;
        if (row >= NROWS) break;
        float acc[4] = {bbv.x, bbv.y, bbv.z, bbv.w};
#pragma unroll
        for (int q = 0; q < 4; q++) {
            float x = sbox[rl][q];
            acc[0] = fmaf(x, wb[q].x, acc[0]); acc[1] = fmaf(x, wb[q].y, acc[1]);
            acc[2] = fmaf(x, wb[q].z, acc[2]); acc[3] = fmaf(x, wb[q].w, acc[3]);
        }
        float acs[4] = {bsv.x, bsv.y, bsv.z, bsv.w};
#pragma unroll
        for (int q = 0; q < 16; q++) {
            float x = ssem[rl][q];
            acs[0] = fmaf(x, ws[q].x, acs[0]); acs[1] = fmaf(x, ws[q].y, acs[1]);
            acs[2] = fmaf(x, ws[q].z, acs[2]); acs[3] = fmaf(x, ws[q].w, acs[3]);
        }
        float v0 = fmaxf(acc[0], 0.f) + fmaxf(acs[0], 0.f);
        float v1 = fmaxf(acc[1], 0.f) + fmaxf(acs[1], 0.f);
        float v2 = fmaxf(acc[2], 0.f) + fmaxf(acs[2], 0.f);
        float v3 = fmaxf(acc[3], 0.f) + fmaxf(acs[3], 0.f);
        __half2 h0 = __floats2half2_rn(v0, v1);
        __half2 h1 = __floats2half2_rn(v2, v3);
        *(uint2*)(g_fA + row * HQ + c) =
            make_uint2(*(uint32_t*)&h0, *(uint32_t*)&h1);
    }
}

// ---------------- common GEMM pieces (R9/R11, unchanged) ----------------
__device__ __forceinline__ void load_stage(
    uint32_t base, int k0, int t, int n0, int tid,
    const __half* __restrict__ src, const int* __restrict__ s_ab) {
#pragma unroll
    for (int i = 0; i < 4; i++) {
        int it = tid + i * 256;
        int row = (it >> 3) & 127;
        int ch = it & 7;
        const __half* sp = src + (size_t)s_ab[row] + k0 + ch * 8;
        uint32_t off = (uint32_t)(row * 128 + ch * 16);
        CP16(base + SWZ(off), sp);
    }
    const __half* wh = g_WT + (size_t)t * HQ * 1280;
    uint32_t bbase = base + 16384;
#pragma unroll
    for (int i = 0; i < 4; i++) {
        int it = tid + i * 256;
        int row = (it >> 3) & 127;
        int ch = it & 7;
        const __half* sp = wh + (size_t)(n0 + row) * 1280 + k0 + ch * 8;
        uint32_t off = (uint32_t)(row * 128 + ch * 16);
        CP16(bbase + SWZ(off), sp);
    }
}

__device__ __forceinline__ void tile_setup(
    char* smem, int lvl, int t, int m0, int n0, int tid,
    const float* __restrict__ Wb, const float* __restrict__ bb,
    const float* __restrict__ bn) {
    int*   s_pr    = (int*)(smem);
    int*   s_ab    = (int*)(smem + 512);
    float* s_wbox  = (float*)(smem + 1024);
    float* s_bbox  = (float*)(smem + 3072);
    float* s_bnode = (float*)(smem + 3584);
    if (tid < TMG) {
        int idx = m0 + tid;
        int lim = g_seg[lvl * 4 + t] + g_count[lvl * 3 + t];
        int pr = (idx < lim) ? g_perm[c_pbase[lvl] + idx] : -1;
        s_pr[tid] = pr;
        s_ab[tid] = (pr < 0 ? 0 : pr) * 1280;
    }
    if (tid < 128) {
#pragma unroll
        for (int q = 0; q < 4; q++) s_wbox[q * 128 + tid] = Wb[q * HQ + n0 + tid];
        s_bbox[tid] = bb[n0 + tid];
        s_bnode[tid] = bn[t * HQ + n0 + tid];
    }
}

__device__ __forceinline__ void epilogue(
    char* smem, float (*acc)[4][4], int wm, int wn, int lid,
    int n, int off, int n0, const float* __restrict__ ibox, __half* __restrict__ dst) {
    int*   s_pr    = (int*)(smem);
    float* s_wbox  = (float*)(smem + 1024);
    float* s_bbox  = (float*)(smem + 3072);
    float* s_bnode = (float*)(smem + 3584);
    int lq = lid >> 2, lr = (lid & 3) * 2;
#pragma unroll
    for (int mt = 0; mt < 4; mt++) {
#pragma unroll
        for (int h2 = 0; h2 < 2; h2++) {
            int m = wm * 64 + mt * 16 + lq + h2 * 8;
            int pr = s_pr[m];
            if (pr < 0) continue;
            int b = pr / n, j = pr - b * n;
            float4 bx = *(const float4*)(ibox + ((size_t)b * NINT + off + j) * 4);
#pragma unroll
            for (int nt = 0; nt < 4; nt++) {
                int cl = wn * 32 + nt * 8 + lr;
                float o[2];
#pragma unroll
                for (int u = 0; u < 2; u++) {
                    float be = s_bbox[cl + u];
                    be = fmaf(bx.x, s_wbox[cl + u], be);
                    be = fmaf(bx.y, s_wbox[128 + cl + u], be);
                    be = fmaf(bx.z, s_wbox[256 + cl + u], be);
                    be = fmaf(bx.w, s_wbox[384 + cl + u], be);
                    float v = acc[mt][nt][h2 * 2 + u] + s_bnode[cl + u];
                    o[u] = fmaxf(v, 0.f) + fmaxf(be, 0.f);
                }
                __half2 hv = __floats2half2_rn(o[0], o[1]);
                *(uint32_t*)(dst + (size_t)pr * HQ + n0 + cl) = *(uint32_t*)&hv;
            }
        }
    }
}

// ---------------- fixed-grid grouped GEMM (big levels; R9-proven) ----------------
__global__ __launch_bounds__(256, 2) void k_tc(
    int srcA, int lvl, int n, int off,
    const float* __restrict__ ibox, const float* __restrict__ bn,
    const float* __restrict__ Wb, const float* __restrict__ bb) {
    extern __shared__ __align__(128) char smem[];
    uint32_t sb = smem_u32(smem);
    int tid = threadIdx.x, wid = tid >> 5, lid = tid & 31;
    int wm = wid & 1, wn = wid >> 1;

    int m0 = blockIdx.y * TMG;
    int total = g_seg[lvl * 4 + 3];
    if (m0 >= total) return;
    int t = (m0 >= g_seg[lvl * 4 + 2]) ? 2 : (m0 >= g_seg[lvl * 4 + 1]) ? 1 : 0;
    int n0 = blockIdx.x * TNG;

    const __half* src = srcA ? g_fA : g_fB;
    __half* dst = srcA ? g_fB : g_fA;

    tile_setup(smem, lvl, t, m0, n0, tid, Wb, bb, bn);
    __syncthreads();

    int* s_ab = (int*)(smem + 512);
    load_stage(sb + 4096, 0, t, n0, tid, src, s_ab);
    CP_COMMIT();
    load_stage(sb + 4096 + STAGE_BYTES, KC, t, n0, tid, src, s_ab);
    CP_COMMIT();

    float acc[4][4][4];
#pragma unroll
    for (int i = 0; i < 4; i++)
#pragma unroll
        for (int j = 0; j < 4; j++)
#pragma unroll
            for (int q = 0; q < 4; q++) acc[i][j][q] = 0.f;

    int a_lrow = lid & 15;
    int a_lcol = (lid >> 4) & 1;
    int b_nrow = (lid & 7) | ((lid >> 1) & 8);
    int b_kcol = (lid >> 3) & 1;

    int stg = 0;
    for (int s = 0; s < NSTAGE; s++) {
        if (s + 2 < NSTAGE) {
            int ns = stg + 2; if (ns >= 3) ns -= 3;
            load_stage(sb + 4096 + ns * STAGE_BYTES, (s + 2) * KC, t, n0, tid, src, s_ab);
        }
        CP_COMMIT();
        CP_WAIT2();
        __syncthreads();

        uint32_t base = sb + 4096 + stg * STAGE_BYTES;
#pragma unroll
        for (int ks = 0; ks < 4; ks++) {
            uint32_t ah[4][4], bh[4][2];
#pragma unroll
            for (int mt = 0; mt < 4; mt++) {
                uint32_t offA = (uint32_t)((wm * 64 + mt * 16 + a_lrow) * 128 + ks * 32 + a_lcol * 16);
                ldm4(base + SWZ(offA), ah[mt]);
            }
#pragma unroll
            for (int np = 0; np < 2; np++) {
                uint32_t offB = (uint32_t)((wn * 32 + np * 16 + b_nrow) * 128 + ks * 32 + b_kcol * 16);
                uint32_t r[4];
                ldm4(base + 16384 + SWZ(offB), r);
                bh[2 * np][0] = r[0]; bh[2 * np][1] = r[1];
                bh[2 * np + 1][0] = r[2]; bh[2 * np + 1][1] = r[3];
            }
#pragma unroll
            for (int mt = 0; mt < 4; mt++)
#pragma unroll
                for (int nt = 0; nt < 4; nt++)
                    mma16816(acc[mt][nt], ah[mt], bh[nt]);
        }
        __syncthreads();
        stg++; if (stg >= 3) stg = 0;
    }

    epilogue(smem, acc, wm, wn, lid, n, off, n0, ibox, dst);
}

// ---------------- TM=32 GEMM for small levels ----------------
// smem: 0 s_pr[32] | 512 s_ab[32] | 1024 wbox | 3072 bbox | 3584 bnode |
//       4096 + stg*20480: {A 4K | B 16K}
__device__ __forceinline__ void load_stage32(
    uint32_t base, int k0, int t, int n0, int tid,
    const __half* __restrict__ src, const int* __restrict__ s_ab) {
    {
        int row = (tid >> 3) & 31;
        int ch = tid & 7;
        const __half* sp = src + (size_t)s_ab[row] + k0 + ch * 8;
        uint32_t off = (uint32_t)(row * 128 + ch * 16);
        CP16(base + SWZ(off), sp);
    }
    const __half* wh = g_WT + (size_t)t * HQ * 1280;
    uint32_t bbase = base + 4096;
#pragma unroll
    for (int i = 0; i < 4; i++) {
        int it = tid + i * 256;
        int row = (it >> 3) & 127;
        int ch = it & 7;
        const __half* sp = wh + (size_t)(n0 + row) * 1280 + k0 + ch * 8;
        uint32_t off = (uint32_t)(row * 128 + ch * 16);
        CP16(bbase + SWZ(off), sp);
    }
}

__global__ __launch_bounds__(256, 2) void k_tc32(
    int srcA, int lvl, int n, int off,
    const float* __restrict__ ibox, const float* __restrict__ bn,
    const float* __restrict__ Wb, const float* __restrict__ bb) {
    extern __shared__ __align__(128) char smem[];
    uint32_t sb = smem_u32(smem);
    int tid = threadIdx.x, wid = tid >> 5, lid = tid & 31;
    int wn = wid;                      // 8 warp-cols x 16 columns

    int m0 = blockIdx.y * 32;
    int total = g_seg[lvl * 4 + 3];
    if (m0 >= total) return;
    int t = (m0 >= g_seg[lvl * 4 + 2]) ? 2 : (m0 >= g_seg[lvl * 4 + 1]) ? 1 : 0;
    int n0 = blockIdx.x * TNG;

    const __half* src = srcA ? g_fA : g_fB;
    __half* dst = srcA ? g_fB : g_fA;

    int*   s_pr    = (int*)(smem);
    int*   s_ab    = (int*)(smem + 512);
    float* s_wbox  = (float*)(smem + 1024);
    float* s_bbox  = (float*)(smem + 3072);
    float* s_bnode = (float*)(smem + 3584);

    if (tid < 32) {
        int idx = m0 + tid;
        int lim = g_seg[lvl * 4 + t] + g_count[lvl * 3 + t];
        int pr = (idx < lim) ? g_perm[c_pbase[lvl] + idx] : -1;
        s_pr[tid] = pr;
        s_ab[tid] = (pr < 0 ? 0 : pr) * 1280;
    }
    if (tid < 128) {
#pragma unroll
        for (int q = 0; q < 4; q++) s_wbox[q * 128 + tid] = Wb[q * HQ + n0 + tid];
        s_bbox[tid] = bb[n0 + tid];
        s_bnode[tid] = bn[t * HQ + n0 + tid];
    }
    __syncthreads();

    load_stage32(sb + 4096, 0, t, n0, tid, src, s_ab);
    CP_COMMIT();
    load_stage32(sb + 4096 + STAGE32, KC, t, n0, tid, src, s_ab);
    CP_COMMIT();

    float acc[2][2][4];
#pragma unroll
    for (int i = 0; i < 2; i++)
#pragma unroll
        for (int j = 0; j < 2; j++)
#pragma unroll
            for (int q = 0; q < 4; q++) acc[i][j][q] = 0.f;

    int a_lrow = lid & 15;
    int a_lcol = (lid >> 4) & 1;
    int b_nrow = (lid & 7) | ((lid >> 1) & 8);
    int b_kcol = (lid >> 3) & 1;

    int stg = 0;
    for (int s = 0; s < NSTAGE; s++) {
        if (s + 2 < NSTAGE) {
            int ns = stg + 2; if (ns >= 3) ns -= 3;
            load_stage32(sb + 4096 + ns * STAGE32, (s + 2) * KC, t, n0, tid, src, s_ab);
        }
        CP_COMMIT();
        CP_WAIT2();
        __syncthreads();

        uint32_t base = sb + 4096 + stg * STAGE32;
#pragma unroll
        for (int ks = 0; ks < 4; ks++) {
            uint32_t ah[2][4], bh[2][2];
#pragma unroll
            for (int mt = 0; mt < 2; mt++) {
                uint32_t offA = (uint32_t)((mt * 16 + a_lrow) * 128 + ks * 32 + a_lcol * 16);
                ldm4(base + SWZ(offA), ah[mt]);
            }
            {
                uint32_t offB = (uint32_t)((wn * 16 + b_nrow) * 128 + ks * 32 + b_kcol * 16);
                uint32_t r[4];
                ldm4(base + 4096 + SWZ(offB), r);
                bh[0][0] = r[0]; bh[0][1] = r[1];
                bh[1][0] = r[2]; bh[1][1] = r[3];
            }
#pragma unroll
            for (int mt = 0; mt < 2; mt++)
#pragma unroll
                for (int nt = 0; nt < 2; nt++)
                    mma16816(acc[mt][nt], ah[mt], bh[nt]);
        }
        __syncthreads();
        stg++; if (stg >= 3) stg = 0;
    }

    // epilogue (warp cols wn*16..+15, rows 0..31)
    int lq = lid >> 2, lr = (lid & 3) * 2;
#pragma unroll
    for (int mt = 0; mt < 2; mt++) {
#pragma unroll
        for (int h2 = 0; h2 < 2; h2++) {
            int m = mt * 16 + lq + h2 * 8;
            int pr = s_pr[m];
            if (pr < 0) continue;
            int b = pr / n, j = pr - b * n;
            float4 bx = *(const float4*)(ibox + ((size_t)b * NINT + off + j) * 4);
#pragma unroll
            for (int nt = 0; nt < 2; nt++) {
                int cl = wn * 16 + nt * 8 + lr;
                float o[2];
#pragma unroll
                for (int u = 0; u < 2; u++) {
                    float be = s_bbox[cl + u];
                    be = fmaf(bx.x, s_wbox[cl + u], be);
                    be = fmaf(bx.y, s_wbox[128 + cl + u], be);
                    be = fmaf(bx.z, s_wbox[256 + cl + u], be);
                    be = fmaf(bx.w, s_wbox[384 + cl + u], be);
                    float v = acc[mt][nt][h2 * 2 + u] + s_bnode[cl + u];
                    o[u] = fmaxf(v, 0.f) + fmaxf(be, 0.f);
                }
                __half2 hv = __floats2half2_rn(o[0], o[1]);
                *(uint32_t*)(dst + (size_t)pr * HQ + n0 + cl) = *(uint32_t*)&hv;
            }
        }
    }
}

// ---------------- VAE head ----------------
__global__ void k_head(const float* __restrict__ eps,
                       const float* __restrict__ W1, const float* __restrict__ b1,
                       const float* __restrict__ Wmu, const float* __restrict__ bmu,
                       const float* __restrict__ Wvar, const float* __restrict__ bvar,
                       float* __restrict__ out) {
    int b = blockIdx.x;
    int h = threadIdx.x;
    __shared__ float sroot[HQ];
    __shared__ float senc[HQ];
    sroot[h] = __half2float(g_fA[b * HQ + h]);
    __syncthreads();
    float a = b1[h];
    for (int k = 0; k < HQ; k++) a = fmaf(sroot[k], W1[k * HQ + h], a);
    senc[h] = fmaxf(a, 0.f);
    __syncthreads();
    float mu = bmu[h], lv = bvar[h];
    for (int k = 0; k < HQ; k++) {
        float e = senc[k];
        mu = fmaf(e, Wmu[k * HQ + h], mu);
        lv = fmaf(e, Wvar[k * HQ + h], lv);
    }
    float stdv = expf(0.5f * lv);
    out[b * 2 * HQ + h] = eps[b * HQ + h] * stdv + mu;
    out[b * 2 * HQ + HQ + h] = 1.f + lv - mu * mu - expf(lv);
}

// ---------------- launch ----------------
extern "C" void kernel_launch(void* const* d_in, const int* in_sizes, int n_in,
                              void* d_out, int out_size) {
    const float* leaf_box     = (const float*)d_in[0];
    const float* leaf_sem     = (const float*)d_in[1];
    const float* internal_box = (const float*)d_in[2];
    const int*   node_type    = (const int*)d_in[3];
    const float* eps          = (const float*)d_in[4];
    const float* W_box        = (const float*)d_in[5];
    const float* b_box        = (const float*)d_in[6];
    const float* W_sem        = (const float*)d_in[7];
    const float* b_sem        = (const float*)d_in[8];
    const float* W_node       = (const float*)d_in[9];
    const float* b_node       = (const float*)d_in[10];
    const float* W1           = (const float*)d_in[11];
    const float* b1           = (const float*)d_in[12];
    const float* Wmu          = (const float*)d_in[13];
    const float* bmu          = (const float*)d_in[14];
    const float* Wvar         = (const float*)d_in[15];
    const float* bvar         = (const float*)d_in[16];
    float* out = (float*)d_out;

    cudaFuncSetAttribute(k_tc, cudaFuncAttributeMaxDynamicSharedMemorySize, SMEM_BYTES);
    cudaFuncSetAttribute(k_tc32, cudaFuncAttributeMaxDynamicSharedMemorySize, SMEM32);

    k_reset<<<1, 64>>>();
    k_count<<<(62496 + 255) / 256, 256>>>(node_type);
    k_scan<<<1, 32>>>();
    k_scatter<<<(62496 + 255) / 256, 256>>>(node_type);
    k_wt<<<960, 256>>>(W_node);
    k_leaf<<<(NROWS + 63) / 64, 256>>>(leaf_box, leaf_sem, W_box, b_box, W_sem, b_sem);

    // big levels: TM=128 kernel
    {
        dim3 g5(2, 394);
        k_tc<<<g5, 256, SMEM_BYTES>>>(1, 5, 3125, 781, internal_box, b_node, W_box, b_box);
        dim3 g4(2, 82);
        k_tc<<<g4, 256, SMEM_BYTES>>>(0, 4, 625, 156, internal_box, b_node, W_box, b_box);
    }
    // small levels: TM=32 kernel (4x blocks, 1/4 serial chain)
    struct Lv { int srcA, lvl, n, off, gy; };
    const Lv lv[4] = {
        {1, 3, 125, 31, 76},
        {0, 2,  25,  6, 28},
        {1, 1,   5,  1, 16},
        {0, 0,   1,  0, 16},
    };
    for (int i = 0; i < 4; i++) {
        dim3 grid(2, lv[i].gy);
        k_tc32<<<grid, 256, SMEM32>>>(lv[i].srcA, lv[i].lvl, lv[i].n, lv[i].off,
                                      internal_box, b_node, W_box, b_box);
    }

    k_head<<<BQ, HQ>>>(eps, W1, b1, Wmu, bmu, Wvar, bvar, out);
}

// round 13
// speedup vs baseline: 1.9489x; 1.0100x over previous
#include <cuda_runtime.h>
#include <cuda_fp16.h>
#include <cstdint>

// ---------------- problem constants ----------------
#define BQ 16
#define HQ 256
#define NLEAF 15625
#define NINT 3906
#define NROWS (BQ * NLEAF)
#define TMG 128
#define TNG 128
#define KC 64
#define NSTAGE 20
#define STAGE_BYTES 32768          // A 16K | B 16K
#define SMEM_BYTES (4096 + 3 * STAGE_BYTES)
#define STAGE32 20480              // A 4K | B 16K
#define SMEM32 (4096 + 3 * STAGE32)
#define STAGE64 24576              // A 8K | B 16K
#define SMEM64 (4096 + 3 * STAGE64)

// ---------------- static device scratch ----------------
__device__ __half g_fA[(size_t)NROWS * HQ];        // 128 MB
__device__ __half g_fB[BQ * 3125 * HQ];
__device__ __half g_WT[3 * HQ * 1280];             // [t][n][k] fp16
__device__ int g_perm[65536];
__device__ int g_count[18];
__device__ int g_cursor[18];
__device__ int g_seg[24];

__constant__ int c_n[6]     = {1, 5, 25, 125, 625, 3125};
__constant__ int c_off[6]   = {0, 1, 6, 31, 156, 781};
__constant__ int c_cumM[7]  = {0, 16, 96, 496, 2496, 12496, 62496};
__constant__ int c_pbase[6] = {0, 512, 1024, 2048, 4608, 15104};

// ---------------- helpers ----------------
__device__ __forceinline__ uint32_t smem_u32(const void* p) {
    uint32_t a;
    asm("{ .reg .u64 t; cvta.to.shared.u64 t, %1; cvt.u32.u64 %0, t; }" : "=r"(a) : "l"(p));
    return a;
}
#define SWZ(x) ((x) ^ (((x) >> 3) & 0x70))

#define CP16(d, s)  asm volatile("cp.async.cg.shared.global [%0], [%1], 16;" :: "r"(d), "l"(s) : "memory")
#define CP_COMMIT() asm volatile("cp.async.commit_group;" ::: "memory")
#define CP_WAIT2()  asm volatile("cp.async.wait_group 2;" ::: "memory")

__device__ __forceinline__ void ldm4(uint32_t addr, uint32_t* r) {
    asm volatile("ldmatrix.sync.aligned.m8n8.x4.shared.b16 {%0,%1,%2,%3}, [%4];"
                 : "=r"(r[0]), "=r"(r[1]), "=r"(r[2]), "=r"(r[3]) : "r"(addr));
}
__device__ __forceinline__ void mma16816(float* c, const uint32_t* a, const uint32_t* b) {
    asm volatile(
        "mma.sync.aligned.m16n8k16.row.col.f32.f16.f16.f32 "
        "{%0,%1,%2,%3}, {%4,%5,%6,%7}, {%8,%9}, {%0,%1,%2,%3};"
        : "+f"(c[0]), "+f"(c[1]), "+f"(c[2]), "+f"(c[3])
        : "r"(a[0]), "r"(a[1]), "r"(a[2]), "r"(a[3]), "r"(b[0]), "r"(b[1]));
}

// ---------------- prep kernels ----------------
__global__ void k_reset() {
    int i = threadIdx.x;
    if (i < 18) { g_count[i] = 0; g_cursor[i] = 0; }
}

__device__ __forceinline__ void decode_row(int r, int& l, int& pr, int& b, int& j) {
    l = 0;
    while (r >= c_cumM[l + 1]) l++;
    pr = r - c_cumM[l];
    int n = c_n[l];
    b = pr / n;
    j = pr - b * n;
}

__global__ void k_count(const int* __restrict__ nt) {
    __shared__ int sc[18];
    int tid = threadIdx.x;
    if (tid < 18) sc[tid] = 0;
    __syncthreads();
    int r = blockIdx.x * blockDim.x + tid;
    if (r < 62496) {
        int l, pr, b, j;
        decode_row(r, l, pr, b, j);
        int t = nt[b * NINT + c_off[l] + j];
        atomicAdd(&sc[l * 3 + t], 1);
    }
    __syncthreads();
    if (tid < 18 && sc[tid]) atomicAdd(&g_count[tid], sc[tid]);
}

__global__ void k_scan() {
    if (threadIdx.x == 0) {
        for (int l = 0; l < 6; l++) {
            int base = 0;
            for (int t = 0; t < 3; t++) {
                g_seg[l * 4 + t] = base;
                base += ((g_count[l * 3 + t] + TMG - 1) / TMG) * TMG;
            }
            g_seg[l * 4 + 3] = base;
        }
    }
}

__global__ void k_scatter(const int* __restrict__ nt) {
    __shared__ int sc[18], sbase[18];
    int tid = threadIdx.x;
    if (tid < 18) sc[tid] = 0;
    __syncthreads();
    int r = blockIdx.x * blockDim.x + tid;
    int lt = -1, lpos = 0, l = 0, pr = 0;
    if (r < 62496) {
        int b, j;
        decode_row(r, l, pr, b, j);
        int t = nt[b * NINT + c_off[l] + j];
        lt = l * 3 + t;
        lpos = atomicAdd(&sc[lt], 1);
    }
    __syncthreads();
    if (tid < 18 && sc[tid]) sbase[tid] = atomicAdd(&g_cursor[tid], sc[tid]);
    __syncthreads();
    if (lt >= 0) {
        int t = lt - l * 3;
        g_perm[c_pbase[l] + g_seg[l * 4 + t] + sbase[lt] + lpos] = pr;
    }
}

// W_node (3,1280,256) -> [t][n][k] fp16, coalesced 32x32 tile transpose
__global__ __launch_bounds__(256) void k_wt(const float* __restrict__ Wn) {
    __shared__ float tile[32][33];
    int bid = blockIdx.x;
    int nb = bid & 7;
    int kb = (bid >> 3) % 40;
    int t  = bid / 320;
    int tx = threadIdx.x & 31;
    int ty = threadIdx.x >> 5;
#pragma unroll
    for (int s = 0; s < 4; s++) {
        int kk = ty + s * 8;
        tile[kk][tx] = Wn[((size_t)t * 1280 + kb * 32 + kk) * HQ + nb * 32 + tx];
    }
    __syncthreads();
#pragma unroll
    for (int s = 0; s < 4; s++) {
        int rr = ty + s * 8;
        g_WT[((size_t)t * HQ + nb * 32 + rr) * 1280 + kb * 32 + tx] =
            __float2half(tile[tx][rr]);
    }
}

// ---------------- leaf encoder: register-cached weights (R11-proven) ----------------
__global__ __launch_bounds__(256) void k_leaf(
    const float* __restrict__ lbox, const float* __restrict__ lsem,
    const float* __restrict__ Wb, const float* __restrict__ bb,
    const float* __restrict__ Ws, const float* __restrict__ bs) {
    __shared__ float sbox[64][4];
    __shared__ float ssem[64][16];
    int tid = threadIdx.x;
    long row0 = (long)blockIdx.x * 64;

    {
        long lim = (long)NROWS * 4;
        if (tid < 256) {
            long gi = row0 * 4 + tid;
            sbox[tid >> 2][tid & 3] = (gi < lim) ? lbox[gi] : 0.f;
        }
        long lim2 = (long)NROWS * 16;
#pragma unroll
        for (int i = tid; i < 1024; i += 256) {
            long gi = row0 * 16 + i;
            ssem[i >> 4][i & 15] = (gi < lim2) ? lsem[gi] : 0.f;
        }
    }
    __syncthreads();

    int colgrp = tid & 63;
    int rowgrp = tid >> 6;
    int c = colgrp * 4;

    float4 wb[4], ws[16];
#pragma unroll
    for (int q = 0; q < 4; q++)  wb[q] = *(const float4*)(Wb + q * HQ + c);
#pragma unroll
    for (int q = 0; q < 16; q++) ws[q] = *(const float4*)(Ws + q * HQ + c);
    float4 bbv = *(const float4*)(bb + c);
    float4 bsv = *(const float4*)(bs + c);

#pragma unroll 4
    for (int rr = 0; rr < 16; rr++) {
        int rl = rowgrp * 16 + rr;
        long row = row0 + rl;
        if (row >= NROWS) break;
        float acc[4] = {bbv.x, bbv.y, bbv.z, bbv.w};
#pragma unroll
        for (int q = 0; q < 4; q++) {
            float x = sbox[rl][q];
            acc[0] = fmaf(x, wb[q].x, acc[0]); acc[1] = fmaf(x, wb[q].y, acc[1]);
            acc[2] = fmaf(x, wb[q].z, acc[2]); acc[3] = fmaf(x, wb[q].w, acc[3]);
        }
        float acs[4] = {bsv.x, bsv.y, bsv.z, bsv.w};
#pragma unroll
        for (int q = 0; q < 16; q++) {
            float x = ssem[rl][q];
            acs[0] = fmaf(x, ws[q].x, acs[0]); acs[1] = fmaf(x, ws[q].y, acs[1]);
            acs[2] = fmaf(x, ws[q].z, acs[2]); acs[3] = fmaf(x, ws[q].w, acs[3]);
        }
        float v0 = fmaxf(acc[0], 0.f) + fmaxf(acs[0], 0.f);
        float v1 = fmaxf(acc[1], 0.f) + fmaxf(acs[1], 0.f);
        float v2 = fmaxf(acc[2], 0.f) + fmaxf(acs[2], 0.f);
        float v3 = fmaxf(acc[3], 0.f) + fmaxf(acs[3], 0.f);
        __half2 h0 = __floats2half2_rn(v0, v1);
        __half2 h1 = __floats2half2_rn(v2, v3);
        *(uint2*)(g_fA + row * HQ + c) =
            make_uint2(*(uint32_t*)&h0, *(uint32_t*)&h1);
    }
}

// ---------------- common GEMM pieces (R9/R11, unchanged) ----------------
__device__ __forceinline__ void load_stage(
    uint32_t base, int k0, int t, int n0, int tid,
    const __half* __restrict__ src, const int* __restrict__ s_ab) {
#pragma unroll
    for (int i = 0; i < 4; i++) {
        int it = tid + i * 256;
        int row = (it >> 3) & 127;
        int ch = it & 7;
        const __half* sp = src + (size_t)s_ab[row] + k0 + ch * 8;
        uint32_t off = (uint32_t)(row * 128 + ch * 16);
        CP16(base + SWZ(off), sp);
    }
    const __half* wh = g_WT + (size_t)t * HQ * 1280;
    uint32_t bbase = base + 16384;
#pragma unroll
    for (int i = 0; i < 4; i++) {
        int it = tid + i * 256;
        int row = (it >> 3) & 127;
        int ch = it & 7;
        const __half* sp = wh + (size_t)(n0 + row) * 1280 + k0 + ch * 8;
        uint32_t off = (uint32_t)(row * 128 + ch * 16);
        CP16(bbase + SWZ(off), sp);
    }
}

__device__ __forceinline__ void tile_setup(
    char* smem, int lvl, int t, int m0, int n0, int tid,
    const float* __restrict__ Wb, const float* __restrict__ bb,
    const float* __restrict__ bn) {
    int*   s_pr    = (int*)(smem);
    int*   s_ab    = (int*)(smem + 512);
    float* s_wbox  = (float*)(smem + 1024);
    float* s_bbox  = (float*)(smem + 3072);
    float* s_bnode = (float*)(smem + 3584);
    if (tid < TMG) {
        int idx = m0 + tid;
        int lim = g_seg[lvl * 4 + t] + g_count[lvl * 3 + t];
        int pr = (idx < lim) ? g_perm[c_pbase[lvl] + idx] : -1;
        s_pr[tid] = pr;
        s_ab[tid] = (pr < 0 ? 0 : pr) * 1280;
    }
    if (tid < 128) {
#pragma unroll
        for (int q = 0; q < 4; q++) s_wbox[q * 128 + tid] = Wb[q * HQ + n0 + tid];
        s_bbox[tid] = bb[n0 + tid];
        s_bnode[tid] = bn[t * HQ + n0 + tid];
    }
}

__device__ __forceinline__ void epilogue(
    char* smem, float (*acc)[4][4], int wm, int wn, int lid,
    int n, int off, int n0, const float* __restrict__ ibox, __half* __restrict__ dst) {
    int*   s_pr    = (int*)(smem);
    float* s_wbox  = (float*)(smem + 1024);
    float* s_bbox  = (float*)(smem + 3072);
    float* s_bnode = (float*)(smem + 3584);
    int lq = lid >> 2, lr = (lid & 3) * 2;
#pragma unroll
    for (int mt = 0; mt < 4; mt++) {
#pragma unroll
        for (int h2 = 0; h2 < 2; h2++) {
            int m = wm * 64 + mt * 16 + lq + h2 * 8;
            int pr = s_pr[m];
            if (pr < 0) continue;
            int b = pr / n, j = pr - b * n;
            float4 bx = *(const float4*)(ibox + ((size_t)b * NINT + off + j) * 4);
#pragma unroll
            for (int nt = 0; nt < 4; nt++) {
                int cl = wn * 32 + nt * 8 + lr;
                float o[2];
#pragma unroll
                for (int u = 0; u < 2; u++) {
                    float be = s_bbox[cl + u];
                    be = fmaf(bx.x, s_wbox[cl + u], be);
                    be = fmaf(bx.y, s_wbox[128 + cl + u], be);
                    be = fmaf(bx.z, s_wbox[256 + cl + u], be);
                    be = fmaf(bx.w, s_wbox[384 + cl + u], be);
                    float v = acc[mt][nt][h2 * 2 + u] + s_bnode[cl + u];
                    o[u] = fmaxf(v, 0.f) + fmaxf(be, 0.f);
                }
                __half2 hv = __floats2half2_rn(o[0], o[1]);
                *(uint32_t*)(dst + (size_t)pr * HQ + n0 + cl) = *(uint32_t*)&hv;
            }
        }
    }
}

// ---------------- fixed-grid grouped GEMM TM=128 (level 5) ----------------
__global__ __launch_bounds__(256, 2) void k_tc(
    int srcA, int lvl, int n, int off,
    const float* __restrict__ ibox, const float* __restrict__ bn,
    const float* __restrict__ Wb, const float* __restrict__ bb) {
    extern __shared__ __align__(128) char smem[];
    uint32_t sb = smem_u32(smem);
    int tid = threadIdx.x, wid = tid >> 5, lid = tid & 31;
    int wm = wid & 1, wn = wid >> 1;

    int m0 = blockIdx.y * TMG;
    int total = g_seg[lvl * 4 + 3];
    if (m0 >= total) return;
    int t = (m0 >= g_seg[lvl * 4 + 2]) ? 2 : (m0 >= g_seg[lvl * 4 + 1]) ? 1 : 0;
    int n0 = blockIdx.x * TNG;

    const __half* src = srcA ? g_fA : g_fB;
    __half* dst = srcA ? g_fB : g_fA;

    tile_setup(smem, lvl, t, m0, n0, tid, Wb, bb, bn);
    __syncthreads();

    int* s_ab = (int*)(smem + 512);
    load_stage(sb + 4096, 0, t, n0, tid, src, s_ab);
    CP_COMMIT();
    load_stage(sb + 4096 + STAGE_BYTES, KC, t, n0, tid, src, s_ab);
    CP_COMMIT();

    float acc[4][4][4];
#pragma unroll
    for (int i = 0; i < 4; i++)
#pragma unroll
        for (int j = 0; j < 4; j++)
#pragma unroll
            for (int q = 0; q < 4; q++) acc[i][j][q] = 0.f;

    int a_lrow = lid & 15;
    int a_lcol = (lid >> 4) & 1;
    int b_nrow = (lid & 7) | ((lid >> 1) & 8);
    int b_kcol = (lid >> 3) & 1;

    int stg = 0;
    for (int s = 0; s < NSTAGE; s++) {
        if (s + 2 < NSTAGE) {
            int ns = stg + 2; if (ns >= 3) ns -= 3;
            load_stage(sb + 4096 + ns * STAGE_BYTES, (s + 2) * KC, t, n0, tid, src, s_ab);
        }
        CP_COMMIT();
        CP_WAIT2();
        __syncthreads();

        uint32_t base = sb + 4096 + stg * STAGE_BYTES;
#pragma unroll
        for (int ks = 0; ks < 4; ks++) {
            uint32_t ah[4][4], bh[4][2];
#pragma unroll
            for (int mt = 0; mt < 4; mt++) {
                uint32_t offA = (uint32_t)((wm * 64 + mt * 16 + a_lrow) * 128 + ks * 32 + a_lcol * 16);
                ldm4(base + SWZ(offA), ah[mt]);
            }
#pragma unroll
            for (int np = 0; np < 2; np++) {
                uint32_t offB = (uint32_t)((wn * 32 + np * 16 + b_nrow) * 128 + ks * 32 + b_kcol * 16);
                uint32_t r[4];
                ldm4(base + 16384 + SWZ(offB), r);
                bh[2 * np][0] = r[0]; bh[2 * np][1] = r[1];
                bh[2 * np + 1][0] = r[2]; bh[2 * np + 1][1] = r[3];
            }
#pragma unroll
            for (int mt = 0; mt < 4; mt++)
#pragma unroll
                for (int nt = 0; nt < 4; nt++)
                    mma16816(acc[mt][nt], ah[mt], bh[nt]);
        }
        __syncthreads();
        stg++; if (stg >= 3) stg = 0;
    }

    epilogue(smem, acc, wm, wn, lid, n, off, n0, ibox, dst);
}

// ---------------- TM=64 GEMM (level 4) ----------------
// smem: 0 s_pr[64] | 512 s_ab[64] | 1024 wbox | 3072 bbox | 3584 bnode |
//       4096 + stg*24576: {A 8K | B 16K}
__device__ __forceinline__ void load_stage64(
    uint32_t base, int k0, int t, int n0, int tid,
    const __half* __restrict__ src, const int* __restrict__ s_ab) {
#pragma unroll
    for (int i = 0; i < 2; i++) {      // A: 512 chunks
        int it = tid + i * 256;
        int row = (it >> 3) & 63;
        int ch = it & 7;
        const __half* sp = src + (size_t)s_ab[row] + k0 + ch * 8;
        uint32_t off = (uint32_t)(row * 128 + ch * 16);
        CP16(base + SWZ(off), sp);
    }
    const __half* wh = g_WT + (size_t)t * HQ * 1280;
    uint32_t bbase = base + 8192;
#pragma unroll
    for (int i = 0; i < 4; i++) {      // B: 1024 chunks
        int it = tid + i * 256;
        int row = (it >> 3) & 127;
        int ch = it & 7;
        const __half* sp = wh + (size_t)(n0 + row) * 1280 + k0 + ch * 8;
        uint32_t off = (uint32_t)(row * 128 + ch * 16);
        CP16(bbase + SWZ(off), sp);
    }
}

__global__ __launch_bounds__(256, 2) void k_tc64(
    int srcA, int lvl, int n, int off,
    const float* __restrict__ ibox, const float* __restrict__ bn,
    const float* __restrict__ Wb, const float* __restrict__ bb) {
    extern __shared__ __align__(128) char smem[];
    uint32_t sb = smem_u32(smem);
    int tid = threadIdx.x, wid = tid >> 5, lid = tid & 31;
    int wm = wid & 1, wn = wid >> 1;   // 2 x 4; warp tile 32x32

    int m0 = blockIdx.y * 64;
    int total = g_seg[lvl * 4 + 3];
    if (m0 >= total) return;
    int t = (m0 >= g_seg[lvl * 4 + 2]) ? 2 : (m0 >= g_seg[lvl * 4 + 1]) ? 1 : 0;
    int n0 = blockIdx.x * TNG;

    const __half* src = srcA ? g_fA : g_fB;
    __half* dst = srcA ? g_fB : g_fA;

    int*   s_pr    = (int*)(smem);
    int*   s_ab    = (int*)(smem + 512);
    float* s_wbox  = (float*)(smem + 1024);
    float* s_bbox  = (float*)(smem + 3072);
    float* s_bnode = (float*)(smem + 3584);

    if (tid < 64) {
        int idx = m0 + tid;
        int lim = g_seg[lvl * 4 + t] + g_count[lvl * 3 + t];
        int pr = (idx < lim) ? g_perm[c_pbase[lvl] + idx] : -1;
        s_pr[tid] = pr;
        s_ab[tid] = (pr < 0 ? 0 : pr) * 1280;
    }
    if (tid < 128) {
#pragma unroll
        for (int q = 0; q < 4; q++) s_wbox[q * 128 + tid] = Wb[q * HQ + n0 + tid];
        s_bbox[tid] = bb[n0 + tid];
        s_bnode[tid] = bn[t * HQ + n0 + tid];
    }
    __syncthreads();

    load_stage64(sb + 4096, 0, t, n0, tid, src, s_ab);
    CP_COMMIT();
    load_stage64(sb + 4096 + STAGE64, KC, t, n0, tid, src, s_ab);
    CP_COMMIT();

    float acc[2][4][4];
#pragma unroll
    for (int i = 0; i < 2; i++)
#pragma unroll
        for (int j = 0; j < 4; j++)
#pragma unroll
            for (int q = 0; q < 4; q++) acc[i][j][q] = 0.f;

    int a_lrow = lid & 15;
    int a_lcol = (lid >> 4) & 1;
    int b_nrow = (lid & 7) | ((lid >> 1) & 8);
    int b_kcol = (lid >> 3) & 1;

    int stg = 0;
    for (int s = 0; s < NSTAGE; s++) {
        if (s + 2 < NSTAGE) {
            int ns = stg + 2; if (ns >= 3) ns -= 3;
            load_stage64(sb + 4096 + ns * STAGE64, (s + 2) * KC, t, n0, tid, src, s_ab);
        }
        CP_COMMIT();
        CP_WAIT2();
        __syncthreads();

        uint32_t base = sb + 4096 + stg * STAGE64;
#pragma unroll
        for (int ks = 0; ks < 4; ks++) {
            uint32_t ah[2][4], bh[4][2];
#pragma unroll
            for (int mt = 0; mt < 2; mt++) {
                uint32_t offA = (uint32_t)((wm * 32 + mt * 16 + a_lrow) * 128 + ks * 32 + a_lcol * 16);
                ldm4(base + SWZ(offA), ah[mt]);
            }
#pragma unroll
            for (int np = 0; np < 2; np++) {
                uint32_t offB = (uint32_t)((wn * 32 + np * 16 + b_nrow) * 128 + ks * 32 + b_kcol * 16);
                uint32_t r[4];
                ldm4(base + 8192 + SWZ(offB), r);
                bh[2 * np][0] = r[0]; bh[2 * np][1] = r[1];
                bh[2 * np + 1][0] = r[2]; bh[2 * np + 1][1] = r[3];
            }
#pragma unroll
            for (int mt = 0; mt < 2; mt++)
#pragma unroll
                for (int nt = 0; nt < 4; nt++)
                    mma16816(acc[mt][nt], ah[mt], bh[nt]);
        }
        __syncthreads();
        stg++; if (stg >= 3) stg = 0;
    }

    // epilogue: rows wm*32 + mt*16 + ..., cols wn*32 + nt*8 + ...
    int lq = lid >> 2, lr = (lid & 3) * 2;
#pragma unroll
    for (int mt = 0; mt < 2; mt++) {
#pragma unroll
        for (int h2 = 0; h2 < 2; h2++) {
            int m = wm * 32 + mt * 16 + lq + h2 * 8;
            int pr = s_pr[m];
            if (pr < 0) continue;
            int b = pr / n, j = pr - b * n;
            float4 bx = *(const float4*)(ibox + ((size_t)b * NINT + off + j) * 4);
#pragma unroll
            for (int nt = 0; nt < 4; nt++) {
                int cl = wn * 32 + nt * 8 + lr;
                float o[2];
#pragma unroll
                for (int u = 0; u < 2; u++) {
                    float be = s_bbox[cl + u];
                    be = fmaf(bx.x, s_wbox[cl + u], be);
                    be = fmaf(bx.y, s_wbox[128 + cl + u], be);
                    be = fmaf(bx.z, s_wbox[256 + cl + u], be);
                    be = fmaf(bx.w, s_wbox[384 + cl + u], be);
                    float v = acc[mt][nt][h2 * 2 + u] + s_bnode[cl + u];
                    o[u] = fmaxf(v, 0.f) + fmaxf(be, 0.f);
                }
                __half2 hv = __floats2half2_rn(o[0], o[1]);
                *(uint32_t*)(dst + (size_t)pr * HQ + n0 + cl) = *(uint32_t*)&hv;
            }
        }
    }
}

// ---------------- TM=32 GEMM for small levels (R12-proven) ----------------
__device__ __forceinline__ void load_stage32(
    uint32_t base, int k0, int t, int n0, int tid,
    const __half* __restrict__ src, const int* __restrict__ s_ab) {
    {
        int row = (tid >> 3) & 31;
        int ch = tid & 7;
        const __half* sp = src + (size_t)s_ab[row] + k0 + ch * 8;
        uint32_t off = (uint32_t)(row * 128 + ch * 16);
        CP16(base + SWZ(off), sp);
    }
    const __half* wh = g_WT + (size_t)t * HQ * 1280;
    uint32_t bbase = base + 4096;
#pragma unroll
    for (int i = 0; i < 4; i++) {
        int it = tid + i * 256;
        int row = (it >> 3) & 127;
        int ch = it & 7;
        const __half* sp = wh + (size_t)(n0 + row) * 1280 + k0 + ch * 8;
        uint32_t off = (uint32_t)(row * 128 + ch * 16);
        CP16(bbase + SWZ(off), sp);
    }
}

__global__ __launch_bounds__(256, 2) void k_tc32(
    int srcA, int lvl, int n, int off,
    const float* __restrict__ ibox, const float* __restrict__ bn,
    const float* __restrict__ Wb, const float* __restrict__ bb) {
    extern __shared__ __align__(128) char smem[];
    uint32_t sb = smem_u32(smem);
    int tid = threadIdx.x, wid = tid >> 5, lid = tid & 31;
    int wn = wid;

    int m0 = blockIdx.y * 32;
    int total = g_seg[lvl * 4 + 3];
    if (m0 >= total) return;
    int t = (m0 >= g_seg[lvl * 4 + 2]) ? 2 : (m0 >= g_seg[lvl * 4 + 1]) ? 1 : 0;
    int n0 = blockIdx.x * TNG;

    const __half* src = srcA ? g_fA : g_fB;
    __half* dst = srcA ? g_fB : g_fA;

    int*   s_pr    = (int*)(smem);
    int*   s_ab    = (int*)(smem + 512);
    float* s_wbox  = (float*)(smem + 1024);
    float* s_bbox  = (float*)(smem + 3072);
    float* s_bnode = (float*)(smem + 3584);

    if (tid < 32) {
        int idx = m0 + tid;
        int lim = g_seg[lvl * 4 + t] + g_count[lvl * 3 + t];
        int pr = (idx < lim) ? g_perm[c_pbase[lvl] + idx] : -1;
        s_pr[tid] = pr;
        s_ab[tid] = (pr < 0 ? 0 : pr) * 1280;
    }
    if (tid < 128) {
#pragma unroll
        for (int q = 0; q < 4; q++) s_wbox[q * 128 + tid] = Wb[q * HQ + n0 + tid];
        s_bbox[tid] = bb[n0 + tid];
        s_bnode[tid] = bn[t * HQ + n0 + tid];
    }
    __syncthreads();

    load_stage32(sb + 4096, 0, t, n0, tid, src, s_ab);
    CP_COMMIT();
    load_stage32(sb + 4096 + STAGE32, KC, t, n0, tid, src, s_ab);
    CP_COMMIT();

    float acc[2][2][4];
#pragma unroll
    for (int i = 0; i < 2; i++)
#pragma unroll
        for (int j = 0; j < 2; j++)
#pragma unroll
            for (int q = 0; q < 4; q++) acc[i][j][q] = 0.f;

    int a_lrow = lid & 15;
    int a_lcol = (lid >> 4) & 1;
    int b_nrow = (lid & 7) | ((lid >> 1) & 8);
    int b_kcol = (lid >> 3) & 1;

    int stg = 0;
    for (int s = 0; s < NSTAGE; s++) {
        if (s + 2 < NSTAGE) {
            int ns = stg + 2; if (ns >= 3) ns -= 3;
            load_stage32(sb + 4096 + ns * STAGE32, (s + 2) * KC, t, n0, tid, src, s_ab);
        }
        CP_COMMIT();
        CP_WAIT2();
        __syncthreads();

        uint32_t base = sb + 4096 + stg * STAGE32;
#pragma unroll
        for (int ks = 0; ks < 4; ks++) {
            uint32_t ah[2][4], bh[2][2];
#pragma unroll
            for (int mt = 0; mt < 2; mt++) {
                uint32_t offA = (uint32_t)((mt * 16 + a_lrow) * 128 + ks * 32 + a_lcol * 16);
                ldm4(base + SWZ(offA), ah[mt]);
            }
            {
                uint32_t offB = (uint32_t)((wn * 16 + b_nrow) * 128 + ks * 32 + b_kcol * 16);
                uint32_t r[4];
                ldm4(base + 4096 + SWZ(offB), r);
                bh[0][0] = r[0]; bh[0][1] = r[1];
                bh[1][0] = r[2]; bh[1][1] = r[3];
            }
#pragma unroll
            for (int mt = 0; mt < 2; mt++)
#pragma unroll
                for (int nt = 0; nt < 2; nt++)
                    mma16816(acc[mt][nt], ah[mt], bh[nt]);
        }
        __syncthreads();
        stg++; if (stg >= 3) stg = 0;
    }

    int lq = lid >> 2, lr = (lid & 3) * 2;
#pragma unroll
    for (int mt = 0; mt < 2; mt++) {
#pragma unroll
        for (int h2 = 0; h2 < 2; h2++) {
            int m = mt * 16 + lq + h2 * 8;
            int pr = s_pr[m];
            if (pr < 0) continue;
            int b = pr / n, j = pr - b * n;
            float4 bx = *(const float4*)(ibox + ((size_t)b * NINT + off + j) * 4);
#pragma unroll
            for (int nt = 0; nt < 2; nt++) {
                int cl = wn * 16 + nt * 8 + lr;
                float o[2];
#pragma unroll
                for (int u = 0; u < 2; u++) {
                    float be = s_bbox[cl + u];
                    be = fmaf(bx.x, s_wbox[cl + u], be);
                    be = fmaf(bx.y, s_wbox[128 + cl + u], be);
                    be = fmaf(bx.z, s_wbox[256 + cl + u], be);
                    be = fmaf(bx.w, s_wbox[384 + cl + u], be);
                    float v = acc[mt][nt][h2 * 2 + u] + s_bnode[cl + u];
                    o[u] = fmaxf(v, 0.f) + fmaxf(be, 0.f);
                }
                __half2 hv = __floats2half2_rn(o[0], o[1]);
                *(uint32_t*)(dst + (size_t)pr * HQ + n0 + cl) = *(uint32_t*)&hv;
            }
        }
    }
}

// ---------------- VAE head ----------------
__global__ void k_head(const float* __restrict__ eps,
                       const float* __restrict__ W1, const float* __restrict__ b1,
                       const float* __restrict__ Wmu, const float* __restrict__ bmu,
                       const float* __restrict__ Wvar, const float* __restrict__ bvar,
                       float* __restrict__ out) {
    int b = blockIdx.x;
    int h = threadIdx.x;
    __shared__ float sroot[HQ];
    __shared__ float senc[HQ];
    sroot[h] = __half2float(g_fA[b * HQ + h]);
    __syncthreads();
    float a = b1[h];
    for (int k = 0; k < HQ; k++) a = fmaf(sroot[k], W1[k * HQ + h], a);
    senc[h] = fmaxf(a, 0.f);
    __syncthreads();
    float mu = bmu[h], lv = bvar[h];
    for (int k = 0; k < HQ; k++) {
        float e = senc[k];
        mu = fmaf(e, Wmu[k * HQ + h], mu);
        lv = fmaf(e, Wvar[k * HQ + h], lv);
    }
    float stdv = expf(0.5f * lv);
    out[b * 2 * HQ + h] = eps[b * HQ + h] * stdv + mu;
    out[b * 2 * HQ + HQ + h] = 1.f + lv - mu * mu - expf(lv);
}

// ---------------- launch ----------------
extern "C" void kernel_launch(void* const* d_in, const int* in_sizes, int n_in,
                              void* d_out, int out_size) {
    const float* leaf_box     = (const float*)d_in[0];
    const float* leaf_sem     = (const float*)d_in[1];
    const float* internal_box = (const float*)d_in[2];
    const int*   node_type    = (const int*)d_in[3];
    const float* eps          = (const float*)d_in[4];
    const float* W_box        = (const float*)d_in[5];
    const float* b_box        = (const float*)d_in[6];
    const float* W_sem        = (const float*)d_in[7];
    const float* b_sem        = (const float*)d_in[8];
    const float* W_node       = (const float*)d_in[9];
    const float* b_node       = (const float*)d_in[10];
    const float* W1           = (const float*)d_in[11];
    const float* b1           = (const float*)d_in[12];
    const float* Wmu          = (const float*)d_in[13];
    const float* bmu          = (const float*)d_in[14];
    const float* Wvar         = (const float*)d_in[15];
    const float* bvar         = (const float*)d_in[16];
    float* out = (float*)d_out;

    cudaFuncSetAttribute(k_tc, cudaFuncAttributeMaxDynamicSharedMemorySize, SMEM_BYTES);
    cudaFuncSetAttribute(k_tc64, cudaFuncAttributeMaxDynamicSharedMemorySize, SMEM64);
    cudaFuncSetAttribute(k_tc32, cudaFuncAttributeMaxDynamicSharedMemorySize, SMEM32);

    k_reset<<<1, 64>>>();
    k_count<<<(62496 + 255) / 256, 256>>>(node_type);
    k_scan<<<1, 32>>>();
    k_scatter<<<(62496 + 255) / 256, 256>>>(node_type);
    k_wt<<<960, 256>>>(W_node);
    k_leaf<<<(NROWS + 63) / 64, 256>>>(leaf_box, leaf_sem, W_box, b_box, W_sem, b_sem);

    // level 5: TM=128 (at MMA-issue floor)
    {
        dim3 g5(2, 394);
        k_tc<<<g5, 256, SMEM_BYTES>>>(1, 5, 3125, 781, internal_box, b_node, W_box, b_box);
    }
    // level 4: TM=64 (328 blocks, ~1.1 waves of half chain)
    {
        dim3 g4(2, 164);
        k_tc64<<<g4, 256, SMEM64>>>(0, 4, 625, 156, internal_box, b_node, W_box, b_box);
    }
    // small levels: TM=32 (R12-proven)
    struct Lv { int srcA, lvl, n, off, gy; };
    const Lv lv[4] = {
        {1, 3, 125, 31, 76},
        {0, 2,  25,  6, 28},
        {1, 1,   5,  1, 16},
        {0, 0,   1,  0, 16},
    };
    for (int i = 0; i < 4; i++) {
        dim3 grid(2, lv[i].gy);
        k_tc32<<<grid, 256, SMEM32>>>(lv[i].srcA, lv[i].lvl, lv[i].n, lv[i].off,
                                      internal_box, b_node, W_box, b_box);
    }

    k_head<<<BQ, HQ>>>(eps, W1, b1, Wmu, bmu, Wvar, bvar, out);
}